// round 11
// baseline (speedup 1.0000x reference)
#include <cuda_runtime.h>
#include <cuda_bf16.h>
#include <math.h>
#include <stdint.h>

// Problem constants
#define BQ   4
#define TQ   256
#define DM   1024
#define NEXP 16
#define DL   64
#define NH   4
#define HD   16
#define NTOK 1024      // B*T
#define SEQL 17        // E+1
#define NASSIGN (NTOK*2)

// ---------------- scratch (device globals; no allocation allowed) ----------
__device__ float g_ef   [NTOK * 1024];
__device__ float g_probs[NTOK * NEXP];
__device__ float g_tw   [NASSIGN];
__device__ int   g_ti   [NASSIGN];
__device__ float g_gctx [BQ * DL];
__device__ float g_gb   [BQ * NEXP];
__device__ int   g_ecnt [NEXP];
__device__ int   g_elist[NEXP * NTOK];
__device__ float g_xmp  [BQ][8][DM];
__device__ __nv_bfloat16 g_xhi[DM * DM];
__device__ __nv_bfloat16 g_xlo[DM * DM];
__device__ __nv_bfloat16 g_whi[DM * DM];
__device__ __nv_bfloat16 g_wlo[DM * DM];

__device__ __forceinline__ float gelu_f(float x) {
    return 0.5f * x * (1.0f + erff(x * 0.70710678118654752440f));
}
__device__ __forceinline__ uint32_t smem_u32(const void* p) {
    return (uint32_t)__cvta_generic_to_shared(p);
}
__device__ __forceinline__ void cp_async8(uint32_t dst, const void* src) {
    asm volatile("cp.async.ca.shared.global [%0], [%1], 8;"
                 :: "r"(dst), "l"(src) : "memory");
}
__device__ __forceinline__ void mma_bf16(float* c, const uint32_t* a,
                                         uint32_t b0, uint32_t b1) {
    asm volatile(
        "mma.sync.aligned.m16n8k16.row.col.f32.bf16.bf16.f32 "
        "{%0,%1,%2,%3}, {%4,%5,%6,%7}, {%8,%9}, {%0,%1,%2,%3};"
        : "+f"(c[0]), "+f"(c[1]), "+f"(c[2]), "+f"(c[3])
        : "r"(a[0]), "r"(a[1]), "r"(a[2]), "r"(a[3]), "r"(b0), "r"(b1));
}
__device__ __forceinline__ void ldsm4(uint32_t* r, uint32_t addr) {
    asm volatile("ldmatrix.sync.aligned.m8n8.x4.shared.b16 {%0,%1,%2,%3}, [%4];"
                 : "=r"(r[0]), "=r"(r[1]), "=r"(r[2]), "=r"(r[3]) : "r"(addr));
}
__device__ __forceinline__ float wsum(float v) {
    #pragma unroll
    for (int o = 16; o; o >>= 1) v += __shfl_xor_sync(0xffffffffu, v, o);
    return v;
}

// ---------------- K0: split X,W to bf16 hi/lo + zero g_ef/out + mean parts -
__global__ void k_split(const float* __restrict__ X, const float* __restrict__ W,
                        float* __restrict__ out, int out_size)
{
    int tid = threadIdx.x;
    int i = blockIdx.x * 256 + tid;
    *(float2*)&g_ef[(size_t)i * 2] = make_float2(0.f, 0.f);
    // zero output (replaces cudaMemset node); 524288 threads x 2 floats
    *(float2*)&out[(size_t)i * 2] = make_float2(0.f, 0.f);
    if (i == 0 && out_size > NTOK * 1024) out[NTOK * 1024] = 0.f;

    const float4* src; __nv_bfloat16 *dh, *dl; int j;
    if (i < 262144) { src = (const float4*)X; dh = g_xhi; dl = g_xlo; j = i; }
    else            { src = (const float4*)W; dh = g_whi; dl = g_wlo; j = i - 262144; }
    float4 v = src[j];
    __nv_bfloat16 h0 = __float2bfloat16(v.x), h1 = __float2bfloat16(v.y);
    __nv_bfloat16 h2 = __float2bfloat16(v.z), h3 = __float2bfloat16(v.w);
    __nv_bfloat16 l0 = __float2bfloat16(v.x - __bfloat162float(h0));
    __nv_bfloat16 l1 = __float2bfloat16(v.y - __bfloat162float(h1));
    __nv_bfloat16 l2 = __float2bfloat16(v.z - __bfloat162float(h2));
    __nv_bfloat16 l3 = __float2bfloat16(v.w - __bfloat162float(h3));
    __nv_bfloat162 hA = __nv_bfloat162(h0, h1), hB = __nv_bfloat162(h2, h3);
    __nv_bfloat162 lA = __nv_bfloat162(l0, l1), lB = __nv_bfloat162(l2, l3);
    uint2 ho, lo;
    ho.x = *(uint32_t*)&hA; ho.y = *(uint32_t*)&hB;
    lo.x = *(uint32_t*)&lA; lo.y = *(uint32_t*)&lB;
    *(uint2*)(dh + (size_t)j * 4) = ho;
    *(uint2*)(dl + (size_t)j * 4) = lo;

    // fused mean partials: blocks 0..31 -> (b = bx>>3, c = bx&7)
    if (blockIdx.x < 32) {
        int b = blockIdx.x >> 3, c = blockIdx.x & 7;
        const float* p0 = X + ((size_t)b * TQ + c * 32) * DM;
        for (int d = tid; d < DM; d += 256) {
            float s = 0.f;
            const float* p = p0 + d;
            #pragma unroll 8
            for (int t = 0; t < 32; ++t) s += p[(size_t)t * DM];
            g_xmp[b][c][d] = s;
        }
    }
}

// ---------------- K2: ef GEMM (blocks 0..511) + global context (512..515) --
#define BK     32
#define TSTR   40
#define KHALF  16
#define EF_TILE   (64 * TSTR)
#define EF_STAGE  (4 * EF_TILE)
#define EF_SMEM   (3 * EF_STAGE * 2)          // 61440 bytes

__global__ void __launch_bounds__(128) k_ef_mma(
    const float* __restrict__ gp_w, const float* __restrict__ gp_b,
    const float* __restrict__ g1_w, const float* __restrict__ g1_b,
    const float* __restrict__ g2_w, const float* __restrict__ g2_b)
{
    extern __shared__ __align__(16) char dsm[];
    int tid = threadIdx.x;

    // ---- fused k_global path (4 blocks) ----
    if (blockIdx.x >= 512) {
        float* xm   = (float*)dsm;
        float* part = xm + DM;
        float* gctx = part + 128;
        float* g1s  = gctx + 64;
        int b = blockIdx.x - 512;
        if (b == 0 && tid < NEXP) g_ecnt[tid] = 0;
        for (int d = tid; d < DM; d += 128) {
            float s = 0.f;
            #pragma unroll
            for (int c = 0; c < 8; ++c) s += g_xmp[b][c][d];
            xm[d] = s * (1.0f / (float)TQ);
        }
        __syncthreads();
        {
            int j = tid >> 1, p = tid & 1;
            float s = 0.f;
            const float* w  = gp_w + (size_t)j * DM + p * 512;
            const float* xp = xm + p * 512;
            #pragma unroll 4
            for (int d = 0; d < 512; ++d) s += xp[d] * w[d];
            part[tid] = s;
        }
        __syncthreads();
        if (tid < DL) {
            float s = part[2*tid] + part[2*tid+1] + gp_b[tid];
            gctx[tid] = s;
            g_gctx[b * DL + tid] = s;
        }
        __syncthreads();
        {
            float s = g1_b[tid];
            const float* w = g1_w + tid * DL;
            #pragma unroll
            for (int d = 0; d < DL; ++d) s += gctx[d] * w[d];
            g1s[tid] = gelu_f(s);
        }
        __syncthreads();
        if (tid < NEXP) {
            float s = g2_b[tid];
            const float* w = g2_w + tid * 128;
            #pragma unroll
            for (int c = 0; c < 128; ++c) s += g1s[c] * w[c];
            g_gb[b * NEXP + tid] = s;
        }
        return;
    }

    // ---- GEMM path ----
    __nv_bfloat16* smb = (__nv_bfloat16*)dsm;
    auto tilep = [&](int s, int t4) { return smb + (s * 4 + t4) * EF_TILE; };

    int wid = tid >> 5, lane = tid & 31;
    int g = lane >> 2, t = lane & 3;
    int wm = (wid & 1) * 32, wn = (wid >> 1) * 32;
    int bx = blockIdx.x;
    int kz = bx >> 8, idx = bx & 255;
    int m0 = (idx >> 4) * 64, n0 = (idx & 15) * 64;
    int kbase = kz * (KHALF * BK);

    int loff = ((lane & 15) * TSTR + (lane >> 4) * 8) * 2;

    const __nv_bfloat16* tsrc[4] = {
        g_xhi + (size_t)m0 * DM + kbase, g_xlo + (size_t)m0 * DM + kbase,
        g_whi + (size_t)n0 * DM + kbase, g_wlo + (size_t)n0 * DM + kbase
    };

    float acc[2][4][4];
    #pragma unroll
    for (int mf = 0; mf < 2; ++mf)
        #pragma unroll
        for (int nf = 0; nf < 4; ++nf)
            #pragma unroll
            for (int q = 0; q < 4; ++q) acc[mf][nf][q] = 0.f;

    auto issue = [&](int c, int s) {
        int k0 = c * BK;
        #pragma unroll
        for (int t4 = 0; t4 < 4; ++t4) {
            const __nv_bfloat16* src = tsrc[t4] + k0;
            __nv_bfloat16* dt = tilep(s, t4);
            #pragma unroll
            for (int jj = 0; jj < 4; ++jj) {
                int u = tid + jj * 128;
                int r = u >> 3, c8 = u & 7;
                cp_async8(smem_u32(dt + r * TSTR + c8 * 4),
                          src + (size_t)r * DM + c8 * 4);
            }
        }
    };

    issue(0, 0); asm volatile("cp.async.commit_group;" ::: "memory");
    issue(1, 1); asm volatile("cp.async.commit_group;" ::: "memory");

    for (int c = 0; c < KHALF; ++c) {
        int bsel = c % 3;
        asm volatile("cp.async.wait_group 1;" ::: "memory");
        __syncthreads();
        if (c + 2 < KHALF) issue(c + 2, (c + 2) % 3);
        asm volatile("cp.async.commit_group;" ::: "memory");

        uint32_t baseAh = smem_u32(tilep(bsel, 0)) + loff;
        uint32_t baseAl = smem_u32(tilep(bsel, 1)) + loff;
        uint32_t baseBh = smem_u32(tilep(bsel, 2)) + loff;
        uint32_t baseBl = smem_u32(tilep(bsel, 3)) + loff;

        uint32_t a0h[2][4], a0l[2][4], b0h[2][4], b0l[2][4];
        uint32_t a1h[2][4], a1l[2][4], b1h[2][4], b1l[2][4];
        #pragma unroll
        for (int mf = 0; mf < 2; ++mf) {
            uint32_t ro = ((wm + mf * 16) * TSTR) * 2;
            ldsm4(a0h[mf], baseAh + ro);        ldsm4(a0l[mf], baseAl + ro);
            ldsm4(a1h[mf], baseAh + ro + 32);   ldsm4(a1l[mf], baseAl + ro + 32);
        }
        #pragma unroll
        for (int G = 0; G < 2; ++G) {
            uint32_t ro = ((wn + G * 16) * TSTR) * 2;
            ldsm4(b0h[G], baseBh + ro);         ldsm4(b0l[G], baseBl + ro);
            ldsm4(b1h[G], baseBh + ro + 32);    ldsm4(b1l[G], baseBl + ro + 32);
        }
        #pragma unroll
        for (int mf = 0; mf < 2; ++mf)
            #pragma unroll
            for (int nf = 0; nf < 4; ++nf) {
                int G = nf >> 1, o = nf & 1;
                mma_bf16(acc[mf][nf], a0h[mf], b0h[G][o], b0h[G][o + 2]);
                mma_bf16(acc[mf][nf], a0h[mf], b0l[G][o], b0l[G][o + 2]);
                mma_bf16(acc[mf][nf], a0l[mf], b0h[G][o], b0h[G][o + 2]);
            }
        #pragma unroll
        for (int mf = 0; mf < 2; ++mf)
            #pragma unroll
            for (int nf = 0; nf < 4; ++nf) {
                int G = nf >> 1, o = nf & 1;
                mma_bf16(acc[mf][nf], a1h[mf], b1h[G][o], b1h[G][o + 2]);
                mma_bf16(acc[mf][nf], a1h[mf], b1l[G][o], b1l[G][o + 2]);
                mma_bf16(acc[mf][nf], a1l[mf], b1h[G][o], b1h[G][o + 2]);
            }
    }

    #pragma unroll
    for (int mf = 0; mf < 2; ++mf) {
        int row = m0 + wm + mf * 16 + g;
        #pragma unroll
        for (int nf = 0; nf < 4; ++nf) {
            int col = n0 + wn + nf * 8 + 2 * t;
            atomicAdd(&g_ef[(size_t)(row    ) * DM + col    ], acc[mf][nf][0]);
            atomicAdd(&g_ef[(size_t)(row    ) * DM + col + 1], acc[mf][nf][1]);
            atomicAdd(&g_ef[(size_t)(row + 8) * DM + col    ], acc[mf][nf][2]);
            atomicAdd(&g_ef[(size_t)(row + 8) * DM + col + 1], acc[mf][nf][3]);
        }
    }
}

// ---------------- K3: per-token micro-transformer + routing ---------------
__global__ void __launch_bounds__(256)
k_token(const float* __restrict__ pos,
        const float* __restrict__ aw, const float* __restrict__ ab,
        const float* __restrict__ ow, const float* __restrict__ ob,
        const float* __restrict__ lnw, const float* __restrict__ lnb,
        const float* __restrict__ lsw, const float* __restrict__ lsb)
{
    __shared__ __align__(16) float seq[SEQL][DL];
    __shared__ __align__(16) float qkv[SEQL][192];
    __shared__ float sc[NH][SEQL][SEQL];
    __shared__ __align__(16) float ctx[SEQL][DL];
    __shared__ __align__(16) float hb[SEQL][DL];
    __shared__ float logits[NEXP];

    int n = blockIdx.x, tid = threadIdx.x;
    int b = n >> 8;

    for (int i = tid; i < NEXP * DL; i += 256)
        seq[1 + (i >> 6)][i & 63] = g_ef[(size_t)n * 1024 + i] + pos[i];
    if (tid < DL) seq[0][tid] = g_gctx[b * DL + tid];
    __syncthreads();

    if (tid < 192) {
        float acc[SEQL];
        #pragma unroll
        for (int i = 0; i < SEQL; ++i) acc[i] = 0.f;
        const float4* w4 = (const float4*)(aw + tid * DL);
        #pragma unroll
        for (int u = 0; u < 16; ++u) {
            float4 wv = w4[u];
            #pragma unroll
            for (int i = 0; i < SEQL; ++i) {
                float4 sv = *(const float4*)&seq[i][u * 4];
                acc[i] += wv.x * sv.x + wv.y * sv.y + wv.z * sv.z + wv.w * sv.w;
            }
        }
        float bias = ab[tid];
        #pragma unroll
        for (int i = 0; i < SEQL; ++i) qkv[i][tid] = acc[i] + bias;
    }
    __syncthreads();

    for (int idx = tid; idx < NH * SEQL * SEQL; idx += 256) {
        int h = idx / (SEQL * SEQL);
        int r = idx % (SEQL * SEQL);
        int i = r / SEQL, j = r % SEQL;
        const float4* qp = (const float4*)&qkv[i][h * HD];
        const float4* kp = (const float4*)&qkv[j][64 + h * HD];
        float s = 0.f;
        #pragma unroll
        for (int u = 0; u < 4; ++u) {
            float4 qv = qp[u], kv = kp[u];
            s += qv.x * kv.x + qv.y * kv.y + qv.z * kv.z + qv.w * kv.w;
        }
        sc[h][i][j] = s * 0.25f;
    }
    __syncthreads();

    if (tid < NH * SEQL) {
        int h = tid / SEQL, i = tid % SEQL;
        float m = -1e30f;
        #pragma unroll
        for (int j = 0; j < SEQL; ++j) m = fmaxf(m, sc[h][i][j]);
        float sum = 0.f;
        #pragma unroll
        for (int j = 0; j < SEQL; ++j) { float e = expf(sc[h][i][j] - m); sc[h][i][j] = e; sum += e; }
        float inv = 1.0f / sum;
        #pragma unroll
        for (int j = 0; j < SEQL; ++j) sc[h][i][j] *= inv;
    }
    __syncthreads();

    for (int idx = tid; idx < SEQL * DL; idx += 256) {
        int i = idx >> 6, d = idx & 63, h = d >> 4;
        float s = 0.f;
        #pragma unroll
        for (int j = 0; j < SEQL; ++j) s += sc[h][i][j] * qkv[j][128 + d];
        ctx[i][d] = s;
    }
    __syncthreads();

    // attn_out + residual: 128 threads, rows partitioned 9+8
    if (tid < 128) {
        int d = tid & 63;
        int i0 = (tid >> 6) ? 9 : 0;
        int i1 = (tid >> 6) ? SEQL : 9;
        float acc[9];
        #pragma unroll
        for (int q = 0; q < 9; ++q) acc[q] = 0.f;
        const float4* w4 = (const float4*)(ow + d * DL);
        #pragma unroll
        for (int u = 0; u < 16; ++u) {
            float4 wv = w4[u];
            for (int i = i0; i < i1; ++i) {
                float4 cv = *(const float4*)&ctx[i][u * 4];
                acc[i - i0] += wv.x * cv.x + wv.y * cv.y + wv.z * cv.z + wv.w * cv.w;
            }
        }
        float bias = ob[d];
        for (int i = i0; i < i1; ++i) hb[i][d] = acc[i - i0] + bias + seq[i][d];
    }
    __syncthreads();

    // LN rows 1..16 fused into logit: warp per 2 rows, shuffle reductions
    {
        int w = tid >> 5, lane = tid & 31;
        #pragma unroll
        for (int rr = 0; rr < 2; ++rr) {
            int i = 1 + (w << 1) + rr;
            float v0 = hb[i][lane], v1 = hb[i][lane + 32];
            float mu = wsum(v0 + v1) * (1.0f / DL);
            float d0 = v0 - mu, d1 = v1 - mu;
            float var = wsum(d0 * d0 + d1 * d1) * (1.0f / DL);
            float rstd = rsqrtf(var + 1e-5f);
            float lp = (d0 * rstd * lnw[lane]      + lnb[lane])      * lsw[lane]
                     + (d1 * rstd * lnw[lane + 32] + lnb[lane + 32]) * lsw[lane + 32];
            lp = wsum(lp);
            if (lane == 0) logits[i - 1] = lp + lsb[0] + g_gb[b * NEXP + (i - 1)];
        }
    }
    __syncthreads();

    if (tid == 0) {
        float m = -1e30f;
        #pragma unroll
        for (int e = 0; e < NEXP; ++e) m = fmaxf(m, logits[e]);
        float p[NEXP]; float sum = 0.f;
        #pragma unroll
        for (int e = 0; e < NEXP; ++e) { p[e] = expf(logits[e] - m); sum += p[e]; }
        float inv = 1.0f / sum;
        float best = -1e30f, sec = -1e30f; int bi = 0, si = 0;
        #pragma unroll
        for (int e = 0; e < NEXP; ++e) {
            float pe = p[e] * inv;
            g_probs[n * NEXP + e] = pe;
            if (pe > best)      { sec = best; si = bi; best = pe; bi = e; }
            else if (pe > sec)  { sec = pe; si = e; }
        }
        float s2 = best + sec;
        g_tw[2*n]   = best / s2;
        g_tw[2*n+1] = sec  / s2;
        g_ti[2*n]   = bi;
        g_ti[2*n+1] = si;
        int p0 = atomicAdd(&g_ecnt[bi], 1); g_elist[bi * NTOK + p0] = 2*n;
        int p1 = atomicAdd(&g_ecnt[si], 1); g_elist[si * NTOK + p1] = 2*n + 1;
    }
}

// ---------------- K4: expert up-projection -> atomicAdd out (+aux) ---------
// Self-contained: computes expert prefix from g_ecnt, maps flat slots to
// g_elist, applies gelu on load. Exactly 2 commutative adds per out element.
__global__ void __launch_bounds__(256)
k_moe2(const float* __restrict__ w_up, float* __restrict__ out, int has_aux)
{
    __shared__ float acts[16][DL];
    __shared__ float wt[DL][64];
    __shared__ int sa[16];
    __shared__ int se[16];
    __shared__ int pre[NEXP];
    __shared__ float partial[NEXP];
    int tid = threadIdx.x;
    int base = blockIdx.x * 16;
    int m0 = blockIdx.y * 64;

    if (tid < NEXP) {
        int o = 0;
        for (int i = 0; i < tid; ++i) o += g_ecnt[i];
        pre[tid] = o;
    }
    __syncthreads();
    if (tid < 16) {
        int f = base + tid;
        int e = 15;
        #pragma unroll
        for (int q = 15; q > 0; --q) if (f < pre[q]) e = q - 1;
        sa[tid] = g_elist[e * NTOK + (f - pre[e])];
        se[tid] = e;
    }
    __syncthreads();
    #pragma unroll
    for (int j = 0; j < 4; ++j) {
        int i = tid + j * 256;
        int slot = i >> 6, d = i & 63;
        int a = sa[slot], e = se[slot];
        acts[slot][d] = gelu_f(g_ef[(size_t)(a >> 1) * 1024 + e * DL + d]);
    }
    __syncthreads();

    int s = 0;
    while (s < 16) {
        int e = se[s];
        int r = s + 1;
        while (r < 16 && se[r] == e) ++r;
        __syncthreads();
        #pragma unroll
        for (int j = 0; j < 16; ++j) {
            int idx = tid + j * 256;
            int d = idx >> 6, cc = idx & 63;
            wt[d][cc] = w_up[(((size_t)e << 6) + d) * 1024 + m0 + cc];
        }
        __syncthreads();
        for (int t0 = s; t0 < r; t0 += 4) {
            int t = t0 + (tid >> 6);
            if (t < r) {
                int col = tid & 63;
                float sum = 0.f;
                #pragma unroll
                for (int d = 0; d < DL; ++d) sum += acts[t][d] * wt[d][col];
                int a = sa[t];
                atomicAdd(&out[(size_t)(a >> 1) * 1024 + m0 + col], g_tw[a] * sum);
            }
        }
        s = r;
    }

    // fused aux loss (block 0,0 only; deterministic fixed-order reduction)
    if (has_aux && blockIdx.x == 0 && blockIdx.y == 0) {
        int w = tid >> 5, lane = tid & 31;
        for (int ee = w; ee < NEXP; ee += 8) {
            float psum = 0.f; int ccnt = 0;
            for (int n = lane; n < NTOK; n += 32) {
                psum += g_probs[n * NEXP + ee];
                ccnt += (g_ti[2*n] == ee) + (g_ti[2*n+1] == ee);
            }
            #pragma unroll
            for (int o = 16; o; o >>= 1) {
                psum += __shfl_down_sync(0xffffffffu, psum, o);
                ccnt += __shfl_down_sync(0xffffffffu, ccnt, o);
            }
            if (lane == 0) partial[ee] = psum * (float)ccnt;
        }
        __syncthreads();
        if (tid == 0) {
            float ssum = 0.f;
            #pragma unroll
            for (int e = 0; e < NEXP; ++e) ssum += partial[e];
            out[NTOK * 1024] = ssum * ((float)NEXP / ((float)NTOK * (float)NTOK));
        }
    }
}

// ---------------- launch ---------------------------------------------------
extern "C" void kernel_launch(void* const* d_in, const int* in_sizes, int n_in,
                              void* d_out, int out_size)
{
    const float* x      = (const float*)d_in[0];
    const float* w_down = (const float*)d_in[1];
    const float* pos    = (const float*)d_in[2];
    const float* gp_w   = (const float*)d_in[3];
    const float* gp_b   = (const float*)d_in[4];
    const float* aw     = (const float*)d_in[5];
    const float* ab     = (const float*)d_in[6];
    const float* ow     = (const float*)d_in[7];
    const float* ob     = (const float*)d_in[8];
    const float* lnw    = (const float*)d_in[9];
    const float* lnb    = (const float*)d_in[10];
    const float* lsw    = (const float*)d_in[11];
    const float* lsb    = (const float*)d_in[12];
    const float* g1w    = (const float*)d_in[13];
    const float* g1b    = (const float*)d_in[14];
    const float* g2w    = (const float*)d_in[15];
    const float* g2b    = (const float*)d_in[16];
    const float* wup    = (const float*)d_in[17];
    float* out = (float*)d_out;

    static int attr_done = 0;
    if (!attr_done) {
        cudaFuncSetAttribute(k_ef_mma, cudaFuncAttributeMaxDynamicSharedMemorySize, EF_SMEM);
        attr_done = 1;
    }

    int has_aux = (out_size > NTOK * 1024) ? 1 : 0;

    k_split  <<<2048, 256>>>(x, w_down, out, out_size);
    k_ef_mma <<<516, 128, EF_SMEM>>>(gp_w, gp_b, g1w, g1b, g2w, g2b);
    k_token  <<<NTOK, 256>>>(pos, aw, ab, ow, ob, lnw, lnb, lsw, lsb);
    k_moe2   <<<dim3(NASSIGN / 16, 16), 256>>>(wup, out, has_aux);
}

// round 12
// speedup vs baseline: 1.1497x; 1.1497x over previous
#include <cuda_runtime.h>
#include <cuda_bf16.h>
#include <math.h>
#include <stdint.h>

// Problem constants
#define BQ   4
#define TQ   256
#define DM   1024
#define NEXP 16
#define DL   64
#define NH   4
#define HD   16
#define NTOK 1024      // B*T
#define SEQL 17        // E+1
#define NASSIGN (NTOK*2)

// ---------------- scratch (device globals; no allocation allowed) ----------
__device__ float g_ef   [NTOK * 1024];
__device__ float g_act  [NASSIGN * DL];
__device__ float g_probs[NTOK * NEXP];
__device__ float g_tw   [NASSIGN];
__device__ int   g_ti   [NASSIGN];
__device__ float g_gctx [BQ * DL];
__device__ float g_gb   [BQ * NEXP];
__device__ int   g_ecnt [NEXP];
__device__ int   g_elist[NEXP * NTOK];
__device__ float g_xmp  [BQ][8][DM];
__device__ __nv_bfloat16 g_xhi[DM * DM];
__device__ __nv_bfloat16 g_xlo[DM * DM];
__device__ __nv_bfloat16 g_whi[DM * DM];
__device__ __nv_bfloat16 g_wlo[DM * DM];

__device__ __forceinline__ float gelu_f(float x) {
    return 0.5f * x * (1.0f + erff(x * 0.70710678118654752440f));
}
__device__ __forceinline__ uint32_t smem_u32(const void* p) {
    return (uint32_t)__cvta_generic_to_shared(p);
}
__device__ __forceinline__ void cp_async8(uint32_t dst, const void* src) {
    asm volatile("cp.async.ca.shared.global [%0], [%1], 8;"
                 :: "r"(dst), "l"(src) : "memory");
}
__device__ __forceinline__ void mma_bf16(float* c, const uint32_t* a,
                                         uint32_t b0, uint32_t b1) {
    asm volatile(
        "mma.sync.aligned.m16n8k16.row.col.f32.bf16.bf16.f32 "
        "{%0,%1,%2,%3}, {%4,%5,%6,%7}, {%8,%9}, {%0,%1,%2,%3};"
        : "+f"(c[0]), "+f"(c[1]), "+f"(c[2]), "+f"(c[3])
        : "r"(a[0]), "r"(a[1]), "r"(a[2]), "r"(a[3]), "r"(b0), "r"(b1));
}
__device__ __forceinline__ void ldsm4(uint32_t* r, uint32_t addr) {
    asm volatile("ldmatrix.sync.aligned.m8n8.x4.shared.b16 {%0,%1,%2,%3}, [%4];"
                 : "=r"(r[0]), "=r"(r[1]), "=r"(r[2]), "=r"(r[3]) : "r"(addr));
}
__device__ __forceinline__ float wsum(float v) {
    #pragma unroll
    for (int o = 16; o; o >>= 1) v += __shfl_xor_sync(0xffffffffu, v, o);
    return v;
}

// ---------------- K0: split X,W to bf16 hi/lo + zero g_ef/out + mean parts -
__global__ void k_split(const float* __restrict__ X, const float* __restrict__ W,
                        float* __restrict__ out, int out_size)
{
    int tid = threadIdx.x;
    int i = blockIdx.x * 256 + tid;
    *(float2*)&g_ef[(size_t)i * 2] = make_float2(0.f, 0.f);
    // zero output (replaces cudaMemset node)
    *(float2*)&out[(size_t)i * 2] = make_float2(0.f, 0.f);
    if (i == 0 && out_size > NTOK * 1024) out[NTOK * 1024] = 0.f;

    const float4* src; __nv_bfloat16 *dh, *dl; int j;
    if (i < 262144) { src = (const float4*)X; dh = g_xhi; dl = g_xlo; j = i; }
    else            { src = (const float4*)W; dh = g_whi; dl = g_wlo; j = i - 262144; }
    float4 v = src[j];
    __nv_bfloat16 h0 = __float2bfloat16(v.x), h1 = __float2bfloat16(v.y);
    __nv_bfloat16 h2 = __float2bfloat16(v.z), h3 = __float2bfloat16(v.w);
    __nv_bfloat16 l0 = __float2bfloat16(v.x - __bfloat162float(h0));
    __nv_bfloat16 l1 = __float2bfloat16(v.y - __bfloat162float(h1));
    __nv_bfloat16 l2 = __float2bfloat16(v.z - __bfloat162float(h2));
    __nv_bfloat16 l3 = __float2bfloat16(v.w - __bfloat162float(h3));
    __nv_bfloat162 hA = __nv_bfloat162(h0, h1), hB = __nv_bfloat162(h2, h3);
    __nv_bfloat162 lA = __nv_bfloat162(l0, l1), lB = __nv_bfloat162(l2, l3);
    uint2 ho, lo;
    ho.x = *(uint32_t*)&hA; ho.y = *(uint32_t*)&hB;
    lo.x = *(uint32_t*)&lA; lo.y = *(uint32_t*)&lB;
    *(uint2*)(dh + (size_t)j * 4) = ho;
    *(uint2*)(dl + (size_t)j * 4) = lo;

    // fused mean partials: blocks 0..31 -> (b = bx>>3, c = bx&7)
    if (blockIdx.x < 32) {
        int b = blockIdx.x >> 3, c = blockIdx.x & 7;
        const float* p0 = X + ((size_t)b * TQ + c * 32) * DM;
        for (int d = tid; d < DM; d += 256) {
            float s = 0.f;
            const float* p = p0 + d;
            #pragma unroll 8
            for (int t = 0; t < 32; ++t) s += p[(size_t)t * DM];
            g_xmp[b][c][d] = s;
        }
    }
}

// ---------------- K2: ef GEMM (blocks 0..511) + global context (512..515) --
#define BK     32
#define TSTR   40
#define KHALF  16
#define EF_TILE   (64 * TSTR)
#define EF_STAGE  (4 * EF_TILE)
#define EF_SMEM   (3 * EF_STAGE * 2)          // 61440 bytes

__global__ void __launch_bounds__(128) k_ef_mma(
    const float* __restrict__ gp_w, const float* __restrict__ gp_b,
    const float* __restrict__ g1_w, const float* __restrict__ g1_b,
    const float* __restrict__ g2_w, const float* __restrict__ g2_b)
{
    extern __shared__ __align__(16) char dsm[];
    int tid = threadIdx.x;

    // ---- fused k_global path (4 blocks) ----
    if (blockIdx.x >= 512) {
        float* xm   = (float*)dsm;
        float* part = xm + DM;
        float* gctx = part + 128;
        float* g1s  = gctx + 64;
        int b = blockIdx.x - 512;
        if (b == 0 && tid < NEXP) g_ecnt[tid] = 0;
        for (int d = tid; d < DM; d += 128) {
            float s = 0.f;
            #pragma unroll
            for (int c = 0; c < 8; ++c) s += g_xmp[b][c][d];
            xm[d] = s * (1.0f / (float)TQ);
        }
        __syncthreads();
        {
            int j = tid >> 1, p = tid & 1;
            float s = 0.f;
            const float* w  = gp_w + (size_t)j * DM + p * 512;
            const float* xp = xm + p * 512;
            #pragma unroll 4
            for (int d = 0; d < 512; ++d) s += xp[d] * w[d];
            part[tid] = s;
        }
        __syncthreads();
        if (tid < DL) {
            float s = part[2*tid] + part[2*tid+1] + gp_b[tid];
            gctx[tid] = s;
            g_gctx[b * DL + tid] = s;
        }
        __syncthreads();
        {
            float s = g1_b[tid];
            const float* w = g1_w + tid * DL;
            #pragma unroll
            for (int d = 0; d < DL; ++d) s += gctx[d] * w[d];
            g1s[tid] = gelu_f(s);
        }
        __syncthreads();
        if (tid < NEXP) {
            float s = g2_b[tid];
            const float* w = g2_w + tid * 128;
            #pragma unroll
            for (int c = 0; c < 128; ++c) s += g1s[c] * w[c];
            g_gb[b * NEXP + tid] = s;
        }
        return;
    }

    // ---- GEMM path ----
    __nv_bfloat16* smb = (__nv_bfloat16*)dsm;
    auto tilep = [&](int s, int t4) { return smb + (s * 4 + t4) * EF_TILE; };

    int wid = tid >> 5, lane = tid & 31;
    int g = lane >> 2, t = lane & 3;
    int wm = (wid & 1) * 32, wn = (wid >> 1) * 32;
    int bx = blockIdx.x;
    int kz = bx >> 8, idx = bx & 255;
    int m0 = (idx >> 4) * 64, n0 = (idx & 15) * 64;
    int kbase = kz * (KHALF * BK);

    int loff = ((lane & 15) * TSTR + (lane >> 4) * 8) * 2;

    const __nv_bfloat16* tsrc[4] = {
        g_xhi + (size_t)m0 * DM + kbase, g_xlo + (size_t)m0 * DM + kbase,
        g_whi + (size_t)n0 * DM + kbase, g_wlo + (size_t)n0 * DM + kbase
    };

    float acc[2][4][4];
    #pragma unroll
    for (int mf = 0; mf < 2; ++mf)
        #pragma unroll
        for (int nf = 0; nf < 4; ++nf)
            #pragma unroll
            for (int q = 0; q < 4; ++q) acc[mf][nf][q] = 0.f;

    auto issue = [&](int c, int s) {
        int k0 = c * BK;
        #pragma unroll
        for (int t4 = 0; t4 < 4; ++t4) {
            const __nv_bfloat16* src = tsrc[t4] + k0;
            __nv_bfloat16* dt = tilep(s, t4);
            #pragma unroll
            for (int jj = 0; jj < 4; ++jj) {
                int u = tid + jj * 128;
                int r = u >> 3, c8 = u & 7;
                cp_async8(smem_u32(dt + r * TSTR + c8 * 4),
                          src + (size_t)r * DM + c8 * 4);
            }
        }
    };

    issue(0, 0); asm volatile("cp.async.commit_group;" ::: "memory");
    issue(1, 1); asm volatile("cp.async.commit_group;" ::: "memory");

    for (int c = 0; c < KHALF; ++c) {
        int bsel = c % 3;
        asm volatile("cp.async.wait_group 1;" ::: "memory");
        __syncthreads();
        if (c + 2 < KHALF) issue(c + 2, (c + 2) % 3);
        asm volatile("cp.async.commit_group;" ::: "memory");

        uint32_t baseAh = smem_u32(tilep(bsel, 0)) + loff;
        uint32_t baseAl = smem_u32(tilep(bsel, 1)) + loff;
        uint32_t baseBh = smem_u32(tilep(bsel, 2)) + loff;
        uint32_t baseBl = smem_u32(tilep(bsel, 3)) + loff;

        uint32_t a0h[2][4], a0l[2][4], b0h[2][4], b0l[2][4];
        uint32_t a1h[2][4], a1l[2][4], b1h[2][4], b1l[2][4];
        #pragma unroll
        for (int mf = 0; mf < 2; ++mf) {
            uint32_t ro = ((wm + mf * 16) * TSTR) * 2;
            ldsm4(a0h[mf], baseAh + ro);        ldsm4(a0l[mf], baseAl + ro);
            ldsm4(a1h[mf], baseAh + ro + 32);   ldsm4(a1l[mf], baseAl + ro + 32);
        }
        #pragma unroll
        for (int G = 0; G < 2; ++G) {
            uint32_t ro = ((wn + G * 16) * TSTR) * 2;
            ldsm4(b0h[G], baseBh + ro);         ldsm4(b0l[G], baseBl + ro);
            ldsm4(b1h[G], baseBh + ro + 32);    ldsm4(b1l[G], baseBl + ro + 32);
        }
        #pragma unroll
        for (int mf = 0; mf < 2; ++mf)
            #pragma unroll
            for (int nf = 0; nf < 4; ++nf) {
                int G = nf >> 1, o = nf & 1;
                mma_bf16(acc[mf][nf], a0h[mf], b0h[G][o], b0h[G][o + 2]);
                mma_bf16(acc[mf][nf], a0h[mf], b0l[G][o], b0l[G][o + 2]);
                mma_bf16(acc[mf][nf], a0l[mf], b0h[G][o], b0h[G][o + 2]);
            }
        #pragma unroll
        for (int mf = 0; mf < 2; ++mf)
            #pragma unroll
            for (int nf = 0; nf < 4; ++nf) {
                int G = nf >> 1, o = nf & 1;
                mma_bf16(acc[mf][nf], a1h[mf], b1h[G][o], b1h[G][o + 2]);
                mma_bf16(acc[mf][nf], a1h[mf], b1l[G][o], b1l[G][o + 2]);
                mma_bf16(acc[mf][nf], a1l[mf], b1h[G][o], b1h[G][o + 2]);
            }
    }

    #pragma unroll
    for (int mf = 0; mf < 2; ++mf) {
        int row = m0 + wm + mf * 16 + g;
        #pragma unroll
        for (int nf = 0; nf < 4; ++nf) {
            int col = n0 + wn + nf * 8 + 2 * t;
            atomicAdd(&g_ef[(size_t)(row    ) * DM + col    ], acc[mf][nf][0]);
            atomicAdd(&g_ef[(size_t)(row    ) * DM + col + 1], acc[mf][nf][1]);
            atomicAdd(&g_ef[(size_t)(row + 8) * DM + col    ], acc[mf][nf][2]);
            atomicAdd(&g_ef[(size_t)(row + 8) * DM + col + 1], acc[mf][nf][3]);
        }
    }
}

// ---------------- K3: per-token micro-transformer + routing ---------------
__global__ void __launch_bounds__(256)
k_token(const float* __restrict__ pos,
        const float* __restrict__ aw, const float* __restrict__ ab,
        const float* __restrict__ ow, const float* __restrict__ ob,
        const float* __restrict__ lnw, const float* __restrict__ lnb,
        const float* __restrict__ lsw, const float* __restrict__ lsb)
{
    __shared__ __align__(16) float seq[SEQL][DL];
    __shared__ __align__(16) float qkv[SEQL][192];
    __shared__ float sc[NH][SEQL][SEQL];
    __shared__ __align__(16) float ctx[SEQL][DL];
    __shared__ __align__(16) float hb[SEQL][DL];
    __shared__ float logits[NEXP];

    int n = blockIdx.x, tid = threadIdx.x;
    int b = n >> 8;

    for (int i = tid; i < NEXP * DL; i += 256)
        seq[1 + (i >> 6)][i & 63] = g_ef[(size_t)n * 1024 + i] + pos[i];
    if (tid < DL) seq[0][tid] = g_gctx[b * DL + tid];
    __syncthreads();

    if (tid < 192) {
        float acc[SEQL];
        #pragma unroll
        for (int i = 0; i < SEQL; ++i) acc[i] = 0.f;
        const float4* w4 = (const float4*)(aw + tid * DL);
        #pragma unroll
        for (int u = 0; u < 16; ++u) {
            float4 wv = w4[u];
            #pragma unroll
            for (int i = 0; i < SEQL; ++i) {
                float4 sv = *(const float4*)&seq[i][u * 4];
                acc[i] += wv.x * sv.x + wv.y * sv.y + wv.z * sv.z + wv.w * sv.w;
            }
        }
        float bias = ab[tid];
        #pragma unroll
        for (int i = 0; i < SEQL; ++i) qkv[i][tid] = acc[i] + bias;
    }
    __syncthreads();

    for (int idx = tid; idx < NH * SEQL * SEQL; idx += 256) {
        int h = idx / (SEQL * SEQL);
        int r = idx % (SEQL * SEQL);
        int i = r / SEQL, j = r % SEQL;
        const float4* qp = (const float4*)&qkv[i][h * HD];
        const float4* kp = (const float4*)&qkv[j][64 + h * HD];
        float s = 0.f;
        #pragma unroll
        for (int u = 0; u < 4; ++u) {
            float4 qv = qp[u], kv = kp[u];
            s += qv.x * kv.x + qv.y * kv.y + qv.z * kv.z + qv.w * kv.w;
        }
        sc[h][i][j] = s * 0.25f;
    }
    __syncthreads();

    if (tid < NH * SEQL) {
        int h = tid / SEQL, i = tid % SEQL;
        float m = -1e30f;
        #pragma unroll
        for (int j = 0; j < SEQL; ++j) m = fmaxf(m, sc[h][i][j]);
        float sum = 0.f;
        #pragma unroll
        for (int j = 0; j < SEQL; ++j) { float e = expf(sc[h][i][j] - m); sc[h][i][j] = e; sum += e; }
        float inv = 1.0f / sum;
        #pragma unroll
        for (int j = 0; j < SEQL; ++j) sc[h][i][j] *= inv;
    }
    __syncthreads();

    for (int idx = tid; idx < SEQL * DL; idx += 256) {
        int i = idx >> 6, d = idx & 63, h = d >> 4;
        float s = 0.f;
        #pragma unroll
        for (int j = 0; j < SEQL; ++j) s += sc[h][i][j] * qkv[j][128 + d];
        ctx[i][d] = s;
    }
    __syncthreads();

    // attn_out + residual (thread = output d; fully unrolled; weights cached)
    if (tid < DL) {
        float acc[SEQL];
        #pragma unroll
        for (int i = 0; i < SEQL; ++i) acc[i] = 0.f;
        const float4* w4 = (const float4*)(ow + tid * DL);
        #pragma unroll
        for (int u = 0; u < 16; ++u) {
            float4 wv = w4[u];
            #pragma unroll
            for (int i = 0; i < SEQL; ++i) {
                float4 cv = *(const float4*)&ctx[i][u * 4];
                acc[i] += wv.x * cv.x + wv.y * cv.y + wv.z * cv.z + wv.w * cv.w;
            }
        }
        float bias = ob[tid];
        #pragma unroll
        for (int i = 0; i < SEQL; ++i) hb[i][tid] = acc[i] + bias + seq[i][tid];
    }
    __syncthreads();

    // LN rows 1..16 fused into logit: warp per 2 rows, shuffle reductions
    {
        int w = tid >> 5, lane = tid & 31;
        #pragma unroll
        for (int rr = 0; rr < 2; ++rr) {
            int i = 1 + (w << 1) + rr;
            float v0 = hb[i][lane], v1 = hb[i][lane + 32];
            float mu = wsum(v0 + v1) * (1.0f / DL);
            float d0 = v0 - mu, d1 = v1 - mu;
            float var = wsum(d0 * d0 + d1 * d1) * (1.0f / DL);
            float rstd = rsqrtf(var + 1e-5f);
            float lp = (d0 * rstd * lnw[lane]      + lnb[lane])      * lsw[lane]
                     + (d1 * rstd * lnw[lane + 32] + lnb[lane + 32]) * lsw[lane + 32];
            lp = wsum(lp);
            if (lane == 0) logits[i - 1] = lp + lsb[0] + g_gb[b * NEXP + (i - 1)];
        }
    }
    __syncthreads();

    if (tid == 0) {
        float m = -1e30f;
        #pragma unroll
        for (int e = 0; e < NEXP; ++e) m = fmaxf(m, logits[e]);
        float p[NEXP]; float sum = 0.f;
        #pragma unroll
        for (int e = 0; e < NEXP; ++e) { p[e] = expf(logits[e] - m); sum += p[e]; }
        float inv = 1.0f / sum;
        float best = -1e30f, sec = -1e30f; int bi = 0, si = 0;
        #pragma unroll
        for (int e = 0; e < NEXP; ++e) {
            float pe = p[e] * inv;
            g_probs[n * NEXP + e] = pe;
            if (pe > best)      { sec = best; si = bi; best = pe; bi = e; }
            else if (pe > sec)  { sec = pe; si = e; }
        }
        float s2 = best + sec;
        g_tw[2*n]   = best / s2;
        g_tw[2*n+1] = sec  / s2;
        g_ti[2*n]   = bi;
        g_ti[2*n+1] = si;
        int p0 = atomicAdd(&g_ecnt[bi], 1); g_elist[bi * NTOK + p0] = 2*n;
        int p1 = atomicAdd(&g_ecnt[si], 1); g_elist[si * NTOK + p1] = 2*n + 1;
    }
    __syncthreads();

    // act = gelu(sel) computed ONCE per assignment
    if (tid < 2 * DL) {
        int k = tid >> 6, d = tid & 63;
        int e = g_ti[2*n + k];
        g_act[(size_t)(2*n + k) * DL + d] = gelu_f(g_ef[(size_t)n * 1024 + e * DL + d]);
    }
}

// ---------------- K4: expert up-projection -> atomicAdd out (+aux) ---------
// Self-contained slot mapping: per-block prefix scan over g_ecnt replaces the
// former k_flat kernel. acts from g_act (gelu precomputed once in k_token).
// Exactly 2 commutative adds per out element -> deterministic.
__global__ void __launch_bounds__(256)
k_moe2(const float* __restrict__ w_up, float* __restrict__ out, int has_aux)
{
    __shared__ float acts[16][DL];
    __shared__ float wt[DL][64];
    __shared__ int sa[16];
    __shared__ int se[16];
    __shared__ int pre[NEXP];
    __shared__ float partial[NEXP];
    int tid = threadIdx.x;
    int base = blockIdx.x * 16;
    int m0 = blockIdx.y * 64;

    if (tid < NEXP) {
        int o = 0;
        for (int i = 0; i < tid; ++i) o += g_ecnt[i];
        pre[tid] = o;
    }
    __syncthreads();
    if (tid < 16) {
        int f = base + tid;
        int e = 15;
        #pragma unroll
        for (int q = 15; q > 0; --q) if (f < pre[q]) e = q - 1;
        sa[tid] = g_elist[e * NTOK + (f - pre[e])];
        se[tid] = e;
    }
    __syncthreads();
    #pragma unroll
    for (int j = 0; j < 4; ++j) {
        int i = tid + j * 256;
        acts[i >> 6][i & 63] = g_act[(size_t)sa[i >> 6] * DL + (i & 63)];
    }
    __syncthreads();

    int s = 0;
    while (s < 16) {
        int e = se[s];
        int r = s + 1;
        while (r < 16 && se[r] == e) ++r;
        __syncthreads();
        #pragma unroll
        for (int j = 0; j < 16; ++j) {
            int idx = tid + j * 256;
            int d = idx >> 6, cc = idx & 63;
            wt[d][cc] = w_up[(((size_t)e << 6) + d) * 1024 + m0 + cc];
        }
        __syncthreads();
        for (int t0 = s; t0 < r; t0 += 4) {
            int t = t0 + (tid >> 6);
            if (t < r) {
                int col = tid & 63;
                float sum = 0.f;
                #pragma unroll
                for (int d = 0; d < DL; ++d) sum += acts[t][d] * wt[d][col];
                int a = sa[t];
                atomicAdd(&out[(size_t)(a >> 1) * 1024 + m0 + col], g_tw[a] * sum);
            }
        }
        s = r;
    }

    // fused aux loss (block 0,0 only; deterministic fixed-order reduction)
    if (has_aux && blockIdx.x == 0 && blockIdx.y == 0) {
        int w = tid >> 5, lane = tid & 31;
        for (int ee = w; ee < NEXP; ee += 8) {
            float psum = 0.f; int ccnt = 0;
            for (int n = lane; n < NTOK; n += 32) {
                psum += g_probs[n * NEXP + ee];
                ccnt += (g_ti[2*n] == ee) + (g_ti[2*n+1] == ee);
            }
            #pragma unroll
            for (int o = 16; o; o >>= 1) {
                psum += __shfl_down_sync(0xffffffffu, psum, o);
                ccnt += __shfl_down_sync(0xffffffffu, ccnt, o);
            }
            if (lane == 0) partial[ee] = psum * (float)ccnt;
        }
        __syncthreads();
        if (tid == 0) {
            float ssum = 0.f;
            #pragma unroll
            for (int e = 0; e < NEXP; ++e) ssum += partial[e];
            out[NTOK * 1024] = ssum * ((float)NEXP / ((float)NTOK * (float)NTOK));
        }
    }
}

// ---------------- launch ---------------------------------------------------
extern "C" void kernel_launch(void* const* d_in, const int* in_sizes, int n_in,
                              void* d_out, int out_size)
{
    const float* x      = (const float*)d_in[0];
    const float* w_down = (const float*)d_in[1];
    const float* pos    = (const float*)d_in[2];
    const float* gp_w   = (const float*)d_in[3];
    const float* gp_b   = (const float*)d_in[4];
    const float* aw     = (const float*)d_in[5];
    const float* ab     = (const float*)d_in[6];
    const float* ow     = (const float*)d_in[7];
    const float* ob     = (const float*)d_in[8];
    const float* lnw    = (const float*)d_in[9];
    const float* lnb    = (const float*)d_in[10];
    const float* lsw    = (const float*)d_in[11];
    const float* lsb    = (const float*)d_in[12];
    const float* g1w    = (const float*)d_in[13];
    const float* g1b    = (const float*)d_in[14];
    const float* g2w    = (const float*)d_in[15];
    const float* g2b    = (const float*)d_in[16];
    const float* wup    = (const float*)d_in[17];
    float* out = (float*)d_out;

    static int attr_done = 0;
    if (!attr_done) {
        cudaFuncSetAttribute(k_ef_mma, cudaFuncAttributeMaxDynamicSharedMemorySize, EF_SMEM);
        attr_done = 1;
    }

    int has_aux = (out_size > NTOK * 1024) ? 1 : 0;

    k_split  <<<2048, 256>>>(x, w_down, out, out_size);
    k_ef_mma <<<516, 128, EF_SMEM>>>(gp_w, gp_b, g1w, g1b, g2w, g2b);
    k_token  <<<NTOK, 256>>>(pos, aw, ab, ow, ob, lnw, lnb, lsw, lsb);
    k_moe2   <<<dim3(NASSIGN / 16, 16), 256>>>(wup, out, has_aux);
}

// round 13
// speedup vs baseline: 1.1893x; 1.0344x over previous
#include <cuda_runtime.h>
#include <cuda_bf16.h>
#include <math.h>
#include <stdint.h>

// Problem constants
#define BQ   4
#define TQ   256
#define DM   1024
#define NEXP 16
#define DL   64
#define NH   4
#define HD   16
#define NTOK 1024      // B*T
#define SEQL 17        // E+1
#define NASSIGN (NTOK*2)

// ---------------- scratch (device globals; no allocation allowed) ----------
__device__ float g_ef   [NTOK * 1024];
__device__ float g_act  [NASSIGN * DL];
__device__ float g_probs[NTOK * NEXP];
__device__ float g_tw   [NASSIGN];
__device__ int   g_ti   [NASSIGN];
__device__ float g_gctx [BQ * DL];
__device__ float g_gb   [BQ * NEXP];
__device__ int   g_ecnt [NEXP];
__device__ int   g_elist[NEXP * NTOK];
__device__ float g_xmp  [BQ][8][DM];
__device__ __nv_bfloat16 g_xhi[DM * DM];
__device__ __nv_bfloat16 g_xlo[DM * DM];
__device__ __nv_bfloat16 g_whi[DM * DM];
__device__ __nv_bfloat16 g_wlo[DM * DM];

__device__ __forceinline__ float gelu_f(float x) {
    return 0.5f * x * (1.0f + erff(x * 0.70710678118654752440f));
}
__device__ __forceinline__ uint32_t smem_u32(const void* p) {
    return (uint32_t)__cvta_generic_to_shared(p);
}
__device__ __forceinline__ void cp_async8(uint32_t dst, const void* src) {
    asm volatile("cp.async.ca.shared.global [%0], [%1], 8;"
                 :: "r"(dst), "l"(src) : "memory");
}
__device__ __forceinline__ void mma_bf16(float* c, const uint32_t* a,
                                         uint32_t b0, uint32_t b1) {
    asm volatile(
        "mma.sync.aligned.m16n8k16.row.col.f32.bf16.bf16.f32 "
        "{%0,%1,%2,%3}, {%4,%5,%6,%7}, {%8,%9}, {%0,%1,%2,%3};"
        : "+f"(c[0]), "+f"(c[1]), "+f"(c[2]), "+f"(c[3])
        : "r"(a[0]), "r"(a[1]), "r"(a[2]), "r"(a[3]), "r"(b0), "r"(b1));
}
__device__ __forceinline__ void ldsm4(uint32_t* r, uint32_t addr) {
    asm volatile("ldmatrix.sync.aligned.m8n8.x4.shared.b16 {%0,%1,%2,%3}, [%4];"
                 : "=r"(r[0]), "=r"(r[1]), "=r"(r[2]), "=r"(r[3]) : "r"(addr));
}
__device__ __forceinline__ float wsum(float v) {
    #pragma unroll
    for (int o = 16; o; o >>= 1) v += __shfl_xor_sync(0xffffffffu, v, o);
    return v;
}

// ---------------- K0: split X,W to bf16 hi/lo + zero g_ef/out + mean parts -
__global__ void k_split(const float* __restrict__ X, const float* __restrict__ W,
                        float* __restrict__ out, int out_size)
{
    int tid = threadIdx.x;
    int i = blockIdx.x * 256 + tid;
    *(float2*)&g_ef[(size_t)i * 2] = make_float2(0.f, 0.f);
    *(float2*)&out[(size_t)i * 2] = make_float2(0.f, 0.f);
    if (i == 0 && out_size > NTOK * 1024) out[NTOK * 1024] = 0.f;

    const float4* src; __nv_bfloat16 *dh, *dl; int j;
    if (i < 262144) { src = (const float4*)X; dh = g_xhi; dl = g_xlo; j = i; }
    else            { src = (const float4*)W; dh = g_whi; dl = g_wlo; j = i - 262144; }
    float4 v = src[j];
    __nv_bfloat16 h0 = __float2bfloat16(v.x), h1 = __float2bfloat16(v.y);
    __nv_bfloat16 h2 = __float2bfloat16(v.z), h3 = __float2bfloat16(v.w);
    __nv_bfloat16 l0 = __float2bfloat16(v.x - __bfloat162float(h0));
    __nv_bfloat16 l1 = __float2bfloat16(v.y - __bfloat162float(h1));
    __nv_bfloat16 l2 = __float2bfloat16(v.z - __bfloat162float(h2));
    __nv_bfloat16 l3 = __float2bfloat16(v.w - __bfloat162float(h3));
    __nv_bfloat162 hA = __nv_bfloat162(h0, h1), hB = __nv_bfloat162(h2, h3);
    __nv_bfloat162 lA = __nv_bfloat162(l0, l1), lB = __nv_bfloat162(l2, l3);
    uint2 ho, lo;
    ho.x = *(uint32_t*)&hA; ho.y = *(uint32_t*)&hB;
    lo.x = *(uint32_t*)&lA; lo.y = *(uint32_t*)&lB;
    *(uint2*)(dh + (size_t)j * 4) = ho;
    *(uint2*)(dl + (size_t)j * 4) = lo;

    if (blockIdx.x < 32) {
        int b = blockIdx.x >> 3, c = blockIdx.x & 7;
        const float* p0 = X + ((size_t)b * TQ + c * 32) * DM;
        for (int d = tid; d < DM; d += 256) {
            float s = 0.f;
            const float* p = p0 + d;
            #pragma unroll 8
            for (int t = 0; t < 32; ++t) s += p[(size_t)t * DM];
            g_xmp[b][c][d] = s;
        }
    }
}

// ---------------- K2: ef GEMM (blocks 0..511) + global context (512..515) --
#define BK     32
#define TSTR   40
#define KHALF  16
#define EF_TILE   (64 * TSTR)
#define EF_STAGE  (4 * EF_TILE)
#define EF_SMEM   (3 * EF_STAGE * 2)          // 61440 bytes

__global__ void __launch_bounds__(128) k_ef_mma(
    const float* __restrict__ gp_w, const float* __restrict__ gp_b,
    const float* __restrict__ g1_w, const float* __restrict__ g1_b,
    const float* __restrict__ g2_w, const float* __restrict__ g2_b)
{
    extern __shared__ __align__(16) char dsm[];
    int tid = threadIdx.x;

    // ---- fused k_global path (4 blocks) ----
    if (blockIdx.x >= 512) {
        float* xm   = (float*)dsm;
        float* part = xm + DM;
        float* gctx = part + 128;
        float* g1s  = gctx + 64;
        int b = blockIdx.x - 512;
        if (b == 0 && tid < NEXP) g_ecnt[tid] = 0;
        for (int d = tid; d < DM; d += 128) {
            float s = 0.f;
            #pragma unroll
            for (int c = 0; c < 8; ++c) s += g_xmp[b][c][d];
            xm[d] = s * (1.0f / (float)TQ);
        }
        __syncthreads();
        {
            int j = tid >> 1, p = tid & 1;
            float s = 0.f;
            const float* w  = gp_w + (size_t)j * DM + p * 512;
            const float* xp = xm + p * 512;
            #pragma unroll 4
            for (int d = 0; d < 512; ++d) s += xp[d] * w[d];
            part[tid] = s;
        }
        __syncthreads();
        if (tid < DL) {
            float s = part[2*tid] + part[2*tid+1] + gp_b[tid];
            gctx[tid] = s;
            g_gctx[b * DL + tid] = s;
        }
        __syncthreads();
        {
            float s = g1_b[tid];
            const float* w = g1_w + tid * DL;
            #pragma unroll
            for (int d = 0; d < DL; ++d) s += gctx[d] * w[d];
            g1s[tid] = gelu_f(s);
        }
        __syncthreads();
        if (tid < NEXP) {
            float s = g2_b[tid];
            const float* w = g2_w + tid * 128;
            #pragma unroll
            for (int c = 0; c < 128; ++c) s += g1s[c] * w[c];
            g_gb[b * NEXP + tid] = s;
        }
        return;
    }

    // ---- GEMM path ----
    __nv_bfloat16* smb = (__nv_bfloat16*)dsm;
    auto tilep = [&](int s, int t4) { return smb + (s * 4 + t4) * EF_TILE; };

    int wid = tid >> 5, lane = tid & 31;
    int g = lane >> 2, t = lane & 3;
    int wm = (wid & 1) * 32, wn = (wid >> 1) * 32;
    int bx = blockIdx.x;
    int kz = bx >> 8, idx = bx & 255;
    int m0 = (idx >> 4) * 64, n0 = (idx & 15) * 64;
    int kbase = kz * (KHALF * BK);

    int loff = ((lane & 15) * TSTR + (lane >> 4) * 8) * 2;

    const __nv_bfloat16* tsrc[4] = {
        g_xhi + (size_t)m0 * DM + kbase, g_xlo + (size_t)m0 * DM + kbase,
        g_whi + (size_t)n0 * DM + kbase, g_wlo + (size_t)n0 * DM + kbase
    };

    float acc[2][4][4];
    #pragma unroll
    for (int mf = 0; mf < 2; ++mf)
        #pragma unroll
        for (int nf = 0; nf < 4; ++nf)
            #pragma unroll
            for (int q = 0; q < 4; ++q) acc[mf][nf][q] = 0.f;

    auto issue = [&](int c, int s) {
        int k0 = c * BK;
        #pragma unroll
        for (int t4 = 0; t4 < 4; ++t4) {
            const __nv_bfloat16* src = tsrc[t4] + k0;
            __nv_bfloat16* dt = tilep(s, t4);
            #pragma unroll
            for (int jj = 0; jj < 4; ++jj) {
                int u = tid + jj * 128;
                int r = u >> 3, c8 = u & 7;
                cp_async8(smem_u32(dt + r * TSTR + c8 * 4),
                          src + (size_t)r * DM + c8 * 4);
            }
        }
    };

    issue(0, 0); asm volatile("cp.async.commit_group;" ::: "memory");
    issue(1, 1); asm volatile("cp.async.commit_group;" ::: "memory");

    for (int c = 0; c < KHALF; ++c) {
        int bsel = c % 3;
        asm volatile("cp.async.wait_group 1;" ::: "memory");
        __syncthreads();
        if (c + 2 < KHALF) issue(c + 2, (c + 2) % 3);
        asm volatile("cp.async.commit_group;" ::: "memory");

        uint32_t baseAh = smem_u32(tilep(bsel, 0)) + loff;
        uint32_t baseAl = smem_u32(tilep(bsel, 1)) + loff;
        uint32_t baseBh = smem_u32(tilep(bsel, 2)) + loff;
        uint32_t baseBl = smem_u32(tilep(bsel, 3)) + loff;

        uint32_t a0h[2][4], a0l[2][4], b0h[2][4], b0l[2][4];
        uint32_t a1h[2][4], a1l[2][4], b1h[2][4], b1l[2][4];
        #pragma unroll
        for (int mf = 0; mf < 2; ++mf) {
            uint32_t ro = ((wm + mf * 16) * TSTR) * 2;
            ldsm4(a0h[mf], baseAh + ro);        ldsm4(a0l[mf], baseAl + ro);
            ldsm4(a1h[mf], baseAh + ro + 32);   ldsm4(a1l[mf], baseAl + ro + 32);
        }
        #pragma unroll
        for (int G = 0; G < 2; ++G) {
            uint32_t ro = ((wn + G * 16) * TSTR) * 2;
            ldsm4(b0h[G], baseBh + ro);         ldsm4(b0l[G], baseBl + ro);
            ldsm4(b1h[G], baseBh + ro + 32);    ldsm4(b1l[G], baseBl + ro + 32);
        }
        #pragma unroll
        for (int mf = 0; mf < 2; ++mf)
            #pragma unroll
            for (int nf = 0; nf < 4; ++nf) {
                int G = nf >> 1, o = nf & 1;
                mma_bf16(acc[mf][nf], a0h[mf], b0h[G][o], b0h[G][o + 2]);
                mma_bf16(acc[mf][nf], a0h[mf], b0l[G][o], b0l[G][o + 2]);
                mma_bf16(acc[mf][nf], a0l[mf], b0h[G][o], b0h[G][o + 2]);
            }
        #pragma unroll
        for (int mf = 0; mf < 2; ++mf)
            #pragma unroll
            for (int nf = 0; nf < 4; ++nf) {
                int G = nf >> 1, o = nf & 1;
                mma_bf16(acc[mf][nf], a1h[mf], b1h[G][o], b1h[G][o + 2]);
                mma_bf16(acc[mf][nf], a1h[mf], b1l[G][o], b1l[G][o + 2]);
                mma_bf16(acc[mf][nf], a1l[mf], b1h[G][o], b1h[G][o + 2]);
            }
    }

    #pragma unroll
    for (int mf = 0; mf < 2; ++mf) {
        int row = m0 + wm + mf * 16 + g;
        #pragma unroll
        for (int nf = 0; nf < 4; ++nf) {
            int col = n0 + wn + nf * 8 + 2 * t;
            atomicAdd(&g_ef[(size_t)(row    ) * DM + col    ], acc[mf][nf][0]);
            atomicAdd(&g_ef[(size_t)(row    ) * DM + col + 1], acc[mf][nf][1]);
            atomicAdd(&g_ef[(size_t)(row + 8) * DM + col    ], acc[mf][nf][2]);
            atomicAdd(&g_ef[(size_t)(row + 8) * DM + col + 1], acc[mf][nf][3]);
        }
    }
}

// ---------------- K3: per-token micro-transformer + routing ---------------
__global__ void __launch_bounds__(256)
k_token(const float* __restrict__ pos,
        const float* __restrict__ aw, const float* __restrict__ ab,
        const float* __restrict__ ow, const float* __restrict__ ob,
        const float* __restrict__ lnw, const float* __restrict__ lnb,
        const float* __restrict__ lsw, const float* __restrict__ lsb)
{
    __shared__ __align__(16) float seq[SEQL][DL];
    __shared__ __align__(16) float qkv[SEQL][192];
    __shared__ float sc[NH][SEQL][SEQL];
    __shared__ __align__(16) float ctx[SEQL][DL];
    __shared__ __align__(16) float hb[SEQL][DL];
    __shared__ float logits[NEXP];

    int n = blockIdx.x, tid = threadIdx.x;
    int b = n >> 8;

    for (int i = tid; i < NEXP * DL; i += 256)
        seq[1 + (i >> 6)][i & 63] = g_ef[(size_t)n * 1024 + i] + pos[i];
    if (tid < DL) seq[0][tid] = g_gctx[b * DL + tid];
    __syncthreads();

    if (tid < 192) {
        float acc[SEQL];
        #pragma unroll
        for (int i = 0; i < SEQL; ++i) acc[i] = 0.f;
        const float4* w4 = (const float4*)(aw + tid * DL);
        #pragma unroll
        for (int u = 0; u < 16; ++u) {
            float4 wv = w4[u];
            #pragma unroll
            for (int i = 0; i < SEQL; ++i) {
                float4 sv = *(const float4*)&seq[i][u * 4];
                acc[i] += wv.x * sv.x + wv.y * sv.y + wv.z * sv.z + wv.w * sv.w;
            }
        }
        float bias = ab[tid];
        #pragma unroll
        for (int i = 0; i < SEQL; ++i) qkv[i][tid] = acc[i] + bias;
    }
    __syncthreads();

    for (int idx = tid; idx < NH * SEQL * SEQL; idx += 256) {
        int h = idx / (SEQL * SEQL);
        int r = idx % (SEQL * SEQL);
        int i = r / SEQL, j = r % SEQL;
        const float4* qp = (const float4*)&qkv[i][h * HD];
        const float4* kp = (const float4*)&qkv[j][64 + h * HD];
        float s = 0.f;
        #pragma unroll
        for (int u = 0; u < 4; ++u) {
            float4 qv = qp[u], kv = kp[u];
            s += qv.x * kv.x + qv.y * kv.y + qv.z * kv.z + qv.w * kv.w;
        }
        sc[h][i][j] = s * 0.25f;
    }
    __syncthreads();

    if (tid < NH * SEQL) {
        int h = tid / SEQL, i = tid % SEQL;
        float m = -1e30f;
        #pragma unroll
        for (int j = 0; j < SEQL; ++j) m = fmaxf(m, sc[h][i][j]);
        float sum = 0.f;
        #pragma unroll
        for (int j = 0; j < SEQL; ++j) { float e = expf(sc[h][i][j] - m); sc[h][i][j] = e; sum += e; }
        float inv = 1.0f / sum;
        #pragma unroll
        for (int j = 0; j < SEQL; ++j) sc[h][i][j] *= inv;
    }
    __syncthreads();

    for (int idx = tid; idx < SEQL * DL; idx += 256) {
        int i = idx >> 6, d = idx & 63, h = d >> 4;
        float s = 0.f;
        #pragma unroll
        for (int j = 0; j < SEQL; ++j) s += sc[h][i][j] * qkv[j][128 + d];
        ctx[i][d] = s;
    }
    __syncthreads();

    // attn_out + residual: 128 threads, rows split 0-8 / 9-16, full unroll
    if (tid < 128) {
        int d = tid & 63;
        const float4* w4 = (const float4*)(ow + d * DL);
        float bias = ob[d];
        if (tid < 64) {
            float acc[9];
            #pragma unroll
            for (int q = 0; q < 9; ++q) acc[q] = 0.f;
            #pragma unroll
            for (int u = 0; u < 16; ++u) {
                float4 wv = w4[u];
                #pragma unroll
                for (int i = 0; i < 9; ++i) {
                    float4 cv = *(const float4*)&ctx[i][u * 4];
                    acc[i] += wv.x * cv.x + wv.y * cv.y + wv.z * cv.z + wv.w * cv.w;
                }
            }
            #pragma unroll
            for (int i = 0; i < 9; ++i) hb[i][d] = acc[i] + bias + seq[i][d];
        } else {
            float acc[8];
            #pragma unroll
            for (int q = 0; q < 8; ++q) acc[q] = 0.f;
            #pragma unroll
            for (int u = 0; u < 16; ++u) {
                float4 wv = w4[u];
                #pragma unroll
                for (int i = 0; i < 8; ++i) {
                    float4 cv = *(const float4*)&ctx[9 + i][u * 4];
                    acc[i] += wv.x * cv.x + wv.y * cv.y + wv.z * cv.z + wv.w * cv.w;
                }
            }
            #pragma unroll
            for (int i = 0; i < 8; ++i) hb[9 + i][d] = acc[i] + bias + seq[9 + i][d];
        }
    }
    __syncthreads();

    // LN rows 1..16 fused into logit: warp per 2 rows, shuffle reductions
    {
        int w = tid >> 5, lane = tid & 31;
        #pragma unroll
        for (int rr = 0; rr < 2; ++rr) {
            int i = 1 + (w << 1) + rr;
            float v0 = hb[i][lane], v1 = hb[i][lane + 32];
            float mu = wsum(v0 + v1) * (1.0f / DL);
            float d0 = v0 - mu, d1 = v1 - mu;
            float var = wsum(d0 * d0 + d1 * d1) * (1.0f / DL);
            float rstd = rsqrtf(var + 1e-5f);
            float lp = (d0 * rstd * lnw[lane]      + lnb[lane])      * lsw[lane]
                     + (d1 * rstd * lnw[lane + 32] + lnb[lane + 32]) * lsw[lane + 32];
            lp = wsum(lp);
            if (lane == 0) logits[i - 1] = lp + lsb[0] + g_gb[b * NEXP + (i - 1)];
        }
    }
    __syncthreads();

    if (tid == 0) {
        float m = -1e30f;
        #pragma unroll
        for (int e = 0; e < NEXP; ++e) m = fmaxf(m, logits[e]);
        float p[NEXP]; float sum = 0.f;
        #pragma unroll
        for (int e = 0; e < NEXP; ++e) { p[e] = expf(logits[e] - m); sum += p[e]; }
        float inv = 1.0f / sum;
        float best = -1e30f, sec = -1e30f; int bi = 0, si = 0;
        #pragma unroll
        for (int e = 0; e < NEXP; ++e) {
            float pe = p[e] * inv;
            g_probs[n * NEXP + e] = pe;
            if (pe > best)      { sec = best; si = bi; best = pe; bi = e; }
            else if (pe > sec)  { sec = pe; si = e; }
        }
        float s2 = best + sec;
        g_tw[2*n]   = best / s2;
        g_tw[2*n+1] = sec  / s2;
        g_ti[2*n]   = bi;
        g_ti[2*n+1] = si;
        int p0 = atomicAdd(&g_ecnt[bi], 1); g_elist[bi * NTOK + p0] = 2*n;
        int p1 = atomicAdd(&g_ecnt[si], 1); g_elist[si * NTOK + p1] = 2*n + 1;
    }
    __syncthreads();

    // act = gelu(sel) computed ONCE per assignment
    if (tid < 2 * DL) {
        int k = tid >> 6, d = tid & 63;
        int e = g_ti[2*n + k];
        g_act[(size_t)(2*n + k) * DL + d] = gelu_f(g_ef[(size_t)n * 1024 + e * DL + d]);
    }
}

// ---------------- K4: expert up-projection -> atomicAdd out (+aux) ---------
// 32 slots per x-block; transposed padded weight tile (wtT[col][d], pad 68)
// -> float4 LDS both operands, conflict-free. Per-block prefix scan maps
// flat slots to g_elist. Exactly 2 commutative adds per out element.
#define MSLOT 32
__global__ void __launch_bounds__(256)
k_moe2(const float* __restrict__ w_up, float* __restrict__ out, int has_aux)
{
    __shared__ __align__(16) float acts[MSLOT][68];
    __shared__ __align__(16) float wtT[64][68];
    __shared__ int sa[MSLOT];
    __shared__ int se[MSLOT];
    __shared__ int pre[NEXP];
    __shared__ float partial[NEXP];
    int tid = threadIdx.x;
    int base = blockIdx.x * MSLOT;
    int m0 = blockIdx.y * 64;

    if (tid < NEXP) {
        int o = 0;
        for (int i = 0; i < tid; ++i) o += g_ecnt[i];
        pre[tid] = o;
    }
    __syncthreads();
    if (tid < MSLOT) {
        int f = base + tid;
        int e = 15;
        #pragma unroll
        for (int q = 15; q > 0; --q) if (f < pre[q]) e = q - 1;
        sa[tid] = g_elist[e * NTOK + (f - pre[e])];
        se[tid] = e;
    }
    __syncthreads();
    // acts: 32 slots x 16 float4
    #pragma unroll
    for (int j = 0; j < 2; ++j) {
        int i = tid + j * 256;
        int slot = i >> 4, d4 = i & 15;
        float4 v = *(const float4*)&g_act[(size_t)sa[slot] * DL + d4 * 4];
        *(float4*)&acts[slot][d4 * 4] = v;
    }
    __syncthreads();

    int s = 0;
    while (s < MSLOT) {
        int e = se[s];
        int r = s + 1;
        while (r < MSLOT && se[r] == e) ++r;
        __syncthreads();
        // wtT[col][d] = w_up[e][d][m0+col]  (coalesced gmem read)
        #pragma unroll
        for (int j = 0; j < 16; ++j) {
            int idx = tid + j * 256;
            int d = idx >> 6, cc = idx & 63;
            wtT[cc][d] = w_up[(((size_t)e << 6) + d) * 1024 + m0 + cc];
        }
        __syncthreads();
        for (int t0 = s; t0 < r; t0 += 4) {
            int t = t0 + (tid >> 6);
            if (t < r) {
                int col = tid & 63;
                float sum = 0.f;
                #pragma unroll
                for (int u = 0; u < 16; ++u) {
                    float4 av = *(const float4*)&acts[t][u * 4];
                    float4 wv = *(const float4*)&wtT[col][u * 4];
                    sum += av.x * wv.x + av.y * wv.y + av.z * wv.z + av.w * wv.w;
                }
                int a = sa[t];
                atomicAdd(&out[(size_t)(a >> 1) * 1024 + m0 + col], g_tw[a] * sum);
            }
        }
        s = r;
    }

    // fused aux loss (block 0,0 only; deterministic fixed-order reduction)
    if (has_aux && blockIdx.x == 0 && blockIdx.y == 0) {
        int w = tid >> 5, lane = tid & 31;
        for (int ee = w; ee < NEXP; ee += 8) {
            float psum = 0.f; int ccnt = 0;
            for (int n = lane; n < NTOK; n += 32) {
                psum += g_probs[n * NEXP + ee];
                ccnt += (g_ti[2*n] == ee) + (g_ti[2*n+1] == ee);
            }
            #pragma unroll
            for (int o = 16; o; o >>= 1) {
                psum += __shfl_down_sync(0xffffffffu, psum, o);
                ccnt += __shfl_down_sync(0xffffffffu, ccnt, o);
            }
            if (lane == 0) partial[ee] = psum * (float)ccnt;
        }
        __syncthreads();
        if (tid == 0) {
            float ssum = 0.f;
            #pragma unroll
            for (int e = 0; e < NEXP; ++e) ssum += partial[e];
            out[NTOK * 1024] = ssum * ((float)NEXP / ((float)NTOK * (float)NTOK));
        }
    }
}

// ---------------- launch ---------------------------------------------------
extern "C" void kernel_launch(void* const* d_in, const int* in_sizes, int n_in,
                              void* d_out, int out_size)
{
    const float* x      = (const float*)d_in[0];
    const float* w_down = (const float*)d_in[1];
    const float* pos    = (const float*)d_in[2];
    const float* gp_w   = (const float*)d_in[3];
    const float* gp_b   = (const float*)d_in[4];
    const float* aw     = (const float*)d_in[5];
    const float* ab     = (const float*)d_in[6];
    const float* ow     = (const float*)d_in[7];
    const float* ob     = (const float*)d_in[8];
    const float* lnw    = (const float*)d_in[9];
    const float* lnb    = (const float*)d_in[10];
    const float* lsw    = (const float*)d_in[11];
    const float* lsb    = (const float*)d_in[12];
    const float* g1w    = (const float*)d_in[13];
    const float* g1b    = (const float*)d_in[14];
    const float* g2w    = (const float*)d_in[15];
    const float* g2b    = (const float*)d_in[16];
    const float* wup    = (const float*)d_in[17];
    float* out = (float*)d_out;

    static int attr_done = 0;
    if (!attr_done) {
        cudaFuncSetAttribute(k_ef_mma, cudaFuncAttributeMaxDynamicSharedMemorySize, EF_SMEM);
        attr_done = 1;
    }

    int has_aux = (out_size > NTOK * 1024) ? 1 : 0;

    k_split  <<<2048, 256>>>(x, w_down, out, out_size);
    k_ef_mma <<<516, 128, EF_SMEM>>>(gp_w, gp_b, g1w, g1b, g2w, g2b);
    k_token  <<<NTOK, 256>>>(pos, aw, ab, ow, ob, lnw, lnb, lsw, lsb);
    k_moe2   <<<dim3(NASSIGN / MSLOT, 16), 256>>>(wup, out, has_aux);
}

// round 14
// speedup vs baseline: 1.2000x; 1.0090x over previous
#include <cuda_runtime.h>
#include <cuda_bf16.h>
#include <math.h>
#include <stdint.h>

// Problem constants
#define BQ   4
#define TQ   256
#define DM   1024
#define NEXP 16
#define DL   64
#define NH   4
#define HD   16
#define NTOK 1024      // B*T
#define SEQL 17        // E+1
#define NASSIGN (NTOK*2)

// ---------------- scratch (device globals; no allocation allowed) ----------
__device__ float g_ef   [NTOK * 1024];
__device__ float g_act  [NASSIGN * DL];
__device__ float g_probs[NTOK * NEXP];
__device__ float g_tw   [NASSIGN];
__device__ int   g_ti   [NASSIGN];
__device__ float g_gctx [BQ * DL];
__device__ float g_gb   [BQ * NEXP];
__device__ int   g_ecnt [NEXP];
__device__ int   g_elist[NEXP * NTOK];
__device__ float g_xmp  [BQ][8][DM];
__device__ __nv_bfloat16 g_xhi[DM * DM];
__device__ __nv_bfloat16 g_xlo[DM * DM];
__device__ __nv_bfloat16 g_whi[DM * DM];
__device__ __nv_bfloat16 g_wlo[DM * DM];

__device__ __forceinline__ float gelu_f(float x) {
    return 0.5f * x * (1.0f + erff(x * 0.70710678118654752440f));
}
__device__ __forceinline__ uint32_t smem_u32(const void* p) {
    return (uint32_t)__cvta_generic_to_shared(p);
}
__device__ __forceinline__ void cp_async8(uint32_t dst, const void* src) {
    asm volatile("cp.async.ca.shared.global [%0], [%1], 8;"
                 :: "r"(dst), "l"(src) : "memory");
}
__device__ __forceinline__ void mma_bf16(float* c, const uint32_t* a,
                                         uint32_t b0, uint32_t b1) {
    asm volatile(
        "mma.sync.aligned.m16n8k16.row.col.f32.bf16.bf16.f32 "
        "{%0,%1,%2,%3}, {%4,%5,%6,%7}, {%8,%9}, {%0,%1,%2,%3};"
        : "+f"(c[0]), "+f"(c[1]), "+f"(c[2]), "+f"(c[3])
        : "r"(a[0]), "r"(a[1]), "r"(a[2]), "r"(a[3]), "r"(b0), "r"(b1));
}
__device__ __forceinline__ void ldsm4(uint32_t* r, uint32_t addr) {
    asm volatile("ldmatrix.sync.aligned.m8n8.x4.shared.b16 {%0,%1,%2,%3}, [%4];"
                 : "=r"(r[0]), "=r"(r[1]), "=r"(r[2]), "=r"(r[3]) : "r"(addr));
}
__device__ __forceinline__ float wsum(float v) {
    #pragma unroll
    for (int o = 16; o; o >>= 1) v += __shfl_xor_sync(0xffffffffu, v, o);
    return v;
}

// ---------------- K0: split X,W to bf16 hi/lo + zero g_ef/out + mean parts -
__global__ void k_split(const float* __restrict__ X, const float* __restrict__ W,
                        float* __restrict__ out, int out_size)
{
    int tid = threadIdx.x;
    int i = blockIdx.x * 256 + tid;
    *(float2*)&g_ef[(size_t)i * 2] = make_float2(0.f, 0.f);
    *(float2*)&out[(size_t)i * 2] = make_float2(0.f, 0.f);
    if (i == 0 && out_size > NTOK * 1024) out[NTOK * 1024] = 0.f;

    const float4* src; __nv_bfloat16 *dh, *dl; int j;
    if (i < 262144) { src = (const float4*)X; dh = g_xhi; dl = g_xlo; j = i; }
    else            { src = (const float4*)W; dh = g_whi; dl = g_wlo; j = i - 262144; }
    float4 v = src[j];
    __nv_bfloat16 h0 = __float2bfloat16(v.x), h1 = __float2bfloat16(v.y);
    __nv_bfloat16 h2 = __float2bfloat16(v.z), h3 = __float2bfloat16(v.w);
    __nv_bfloat16 l0 = __float2bfloat16(v.x - __bfloat162float(h0));
    __nv_bfloat16 l1 = __float2bfloat16(v.y - __bfloat162float(h1));
    __nv_bfloat16 l2 = __float2bfloat16(v.z - __bfloat162float(h2));
    __nv_bfloat16 l3 = __float2bfloat16(v.w - __bfloat162float(h3));
    __nv_bfloat162 hA = __nv_bfloat162(h0, h1), hB = __nv_bfloat162(h2, h3);
    __nv_bfloat162 lA = __nv_bfloat162(l0, l1), lB = __nv_bfloat162(l2, l3);
    uint2 ho, lo;
    ho.x = *(uint32_t*)&hA; ho.y = *(uint32_t*)&hB;
    lo.x = *(uint32_t*)&lA; lo.y = *(uint32_t*)&lB;
    *(uint2*)(dh + (size_t)j * 4) = ho;
    *(uint2*)(dl + (size_t)j * 4) = lo;

    if (blockIdx.x < 32) {
        int b = blockIdx.x >> 3, c = blockIdx.x & 7;
        const float* p0 = X + ((size_t)b * TQ + c * 32) * DM;
        for (int d = tid; d < DM; d += 256) {
            float s = 0.f;
            const float* p = p0 + d;
            #pragma unroll 8
            for (int t = 0; t < 32; ++t) s += p[(size_t)t * DM];
            g_xmp[b][c][d] = s;
        }
    }
}

// ---------------- K2: ef GEMM (blocks 0..511) + global context (512..515) --
#define BK     32
#define TSTR   40
#define KHALF  16
#define EF_TILE   (64 * TSTR)
#define EF_STAGE  (4 * EF_TILE)
#define EF_SMEM   (3 * EF_STAGE * 2)          // 61440 bytes

__global__ void __launch_bounds__(128) k_ef_mma(
    const float* __restrict__ gp_w, const float* __restrict__ gp_b,
    const float* __restrict__ g1_w, const float* __restrict__ g1_b,
    const float* __restrict__ g2_w, const float* __restrict__ g2_b)
{
    extern __shared__ __align__(16) char dsm[];
    int tid = threadIdx.x;

    // ---- fused k_global path (4 blocks) ----
    if (blockIdx.x >= 512) {
        float* xm   = (float*)dsm;
        float* part = xm + DM;
        float* gctx = part + 128;
        float* g1s  = gctx + 64;
        int b = blockIdx.x - 512;
        if (b == 0 && tid < NEXP) g_ecnt[tid] = 0;
        for (int d = tid; d < DM; d += 128) {
            float s = 0.f;
            #pragma unroll
            for (int c = 0; c < 8; ++c) s += g_xmp[b][c][d];
            xm[d] = s * (1.0f / (float)TQ);
        }
        __syncthreads();
        {
            int j = tid >> 1, p = tid & 1;
            float s = 0.f;
            const float* w  = gp_w + (size_t)j * DM + p * 512;
            const float* xp = xm + p * 512;
            #pragma unroll 4
            for (int d = 0; d < 512; ++d) s += xp[d] * w[d];
            part[tid] = s;
        }
        __syncthreads();
        if (tid < DL) {
            float s = part[2*tid] + part[2*tid+1] + gp_b[tid];
            gctx[tid] = s;
            g_gctx[b * DL + tid] = s;
        }
        __syncthreads();
        {
            float s = g1_b[tid];
            const float* w = g1_w + tid * DL;
            #pragma unroll
            for (int d = 0; d < DL; ++d) s += gctx[d] * w[d];
            g1s[tid] = gelu_f(s);
        }
        __syncthreads();
        if (tid < NEXP) {
            float s = g2_b[tid];
            const float* w = g2_w + tid * 128;
            #pragma unroll
            for (int c = 0; c < 128; ++c) s += g1s[c] * w[c];
            g_gb[b * NEXP + tid] = s;
        }
        return;
    }

    // ---- GEMM path ----
    __nv_bfloat16* smb = (__nv_bfloat16*)dsm;
    auto tilep = [&](int s, int t4) { return smb + (s * 4 + t4) * EF_TILE; };

    int wid = tid >> 5, lane = tid & 31;
    int g = lane >> 2, t = lane & 3;
    int wm = (wid & 1) * 32, wn = (wid >> 1) * 32;
    int bx = blockIdx.x;
    int kz = bx >> 8, idx = bx & 255;
    int m0 = (idx >> 4) * 64, n0 = (idx & 15) * 64;
    int kbase = kz * (KHALF * BK);

    int loff = ((lane & 15) * TSTR + (lane >> 4) * 8) * 2;

    const __nv_bfloat16* tsrc[4] = {
        g_xhi + (size_t)m0 * DM + kbase, g_xlo + (size_t)m0 * DM + kbase,
        g_whi + (size_t)n0 * DM + kbase, g_wlo + (size_t)n0 * DM + kbase
    };

    float acc[2][4][4];
    #pragma unroll
    for (int mf = 0; mf < 2; ++mf)
        #pragma unroll
        for (int nf = 0; nf < 4; ++nf)
            #pragma unroll
            for (int q = 0; q < 4; ++q) acc[mf][nf][q] = 0.f;

    auto issue = [&](int c, int s) {
        int k0 = c * BK;
        #pragma unroll
        for (int t4 = 0; t4 < 4; ++t4) {
            const __nv_bfloat16* src = tsrc[t4] + k0;
            __nv_bfloat16* dt = tilep(s, t4);
            #pragma unroll
            for (int jj = 0; jj < 4; ++jj) {
                int u = tid + jj * 128;
                int r = u >> 3, c8 = u & 7;
                cp_async8(smem_u32(dt + r * TSTR + c8 * 4),
                          src + (size_t)r * DM + c8 * 4);
            }
        }
    };

    issue(0, 0); asm volatile("cp.async.commit_group;" ::: "memory");
    issue(1, 1); asm volatile("cp.async.commit_group;" ::: "memory");

    for (int c = 0; c < KHALF; ++c) {
        int bsel = c % 3;
        asm volatile("cp.async.wait_group 1;" ::: "memory");
        __syncthreads();
        if (c + 2 < KHALF) issue(c + 2, (c + 2) % 3);
        asm volatile("cp.async.commit_group;" ::: "memory");

        uint32_t baseAh = smem_u32(tilep(bsel, 0)) + loff;
        uint32_t baseAl = smem_u32(tilep(bsel, 1)) + loff;
        uint32_t baseBh = smem_u32(tilep(bsel, 2)) + loff;
        uint32_t baseBl = smem_u32(tilep(bsel, 3)) + loff;

        uint32_t a0h[2][4], a0l[2][4], b0h[2][4], b0l[2][4];
        uint32_t a1h[2][4], a1l[2][4], b1h[2][4], b1l[2][4];
        #pragma unroll
        for (int mf = 0; mf < 2; ++mf) {
            uint32_t ro = ((wm + mf * 16) * TSTR) * 2;
            ldsm4(a0h[mf], baseAh + ro);        ldsm4(a0l[mf], baseAl + ro);
            ldsm4(a1h[mf], baseAh + ro + 32);   ldsm4(a1l[mf], baseAl + ro + 32);
        }
        #pragma unroll
        for (int G = 0; G < 2; ++G) {
            uint32_t ro = ((wn + G * 16) * TSTR) * 2;
            ldsm4(b0h[G], baseBh + ro);         ldsm4(b0l[G], baseBl + ro);
            ldsm4(b1h[G], baseBh + ro + 32);    ldsm4(b1l[G], baseBl + ro + 32);
        }
        #pragma unroll
        for (int mf = 0; mf < 2; ++mf)
            #pragma unroll
            for (int nf = 0; nf < 4; ++nf) {
                int G = nf >> 1, o = nf & 1;
                mma_bf16(acc[mf][nf], a0h[mf], b0h[G][o], b0h[G][o + 2]);
                mma_bf16(acc[mf][nf], a0h[mf], b0l[G][o], b0l[G][o + 2]);
                mma_bf16(acc[mf][nf], a0l[mf], b0h[G][o], b0h[G][o + 2]);
            }
        #pragma unroll
        for (int mf = 0; mf < 2; ++mf)
            #pragma unroll
            for (int nf = 0; nf < 4; ++nf) {
                int G = nf >> 1, o = nf & 1;
                mma_bf16(acc[mf][nf], a1h[mf], b1h[G][o], b1h[G][o + 2]);
                mma_bf16(acc[mf][nf], a1h[mf], b1l[G][o], b1l[G][o + 2]);
                mma_bf16(acc[mf][nf], a1l[mf], b1h[G][o], b1h[G][o + 2]);
            }
    }

    #pragma unroll
    for (int mf = 0; mf < 2; ++mf) {
        int row = m0 + wm + mf * 16 + g;
        #pragma unroll
        for (int nf = 0; nf < 4; ++nf) {
            int col = n0 + wn + nf * 8 + 2 * t;
            atomicAdd(&g_ef[(size_t)(row    ) * DM + col    ], acc[mf][nf][0]);
            atomicAdd(&g_ef[(size_t)(row    ) * DM + col + 1], acc[mf][nf][1]);
            atomicAdd(&g_ef[(size_t)(row + 8) * DM + col    ], acc[mf][nf][2]);
            atomicAdd(&g_ef[(size_t)(row + 8) * DM + col + 1], acc[mf][nf][3]);
        }
    }
}

// ---------------- K3: per-token micro-transformer + routing ---------------
__global__ void __launch_bounds__(256)
k_token(const float* __restrict__ pos,
        const float* __restrict__ aw, const float* __restrict__ ab,
        const float* __restrict__ ow, const float* __restrict__ ob,
        const float* __restrict__ lnw, const float* __restrict__ lnb,
        const float* __restrict__ lsw, const float* __restrict__ lsb)
{
    __shared__ __align__(16) float seq[SEQL][DL];
    __shared__ __align__(16) float qkv[SEQL][192];
    __shared__ float sc[NH][SEQL][SEQL];
    __shared__ __align__(16) float ctx[SEQL][DL];
    __shared__ __align__(16) float hb[SEQL][DL];
    __shared__ float logits[NEXP];

    int n = blockIdx.x, tid = threadIdx.x;
    int b = n >> 8;

    for (int i = tid; i < NEXP * DL; i += 256)
        seq[1 + (i >> 6)][i & 63] = g_ef[(size_t)n * 1024 + i] + pos[i];
    if (tid < DL) seq[0][tid] = g_gctx[b * DL + tid];
    __syncthreads();

    if (tid < 192) {
        float acc[SEQL];
        #pragma unroll
        for (int i = 0; i < SEQL; ++i) acc[i] = 0.f;
        const float4* w4 = (const float4*)(aw + tid * DL);
        #pragma unroll
        for (int u = 0; u < 16; ++u) {
            float4 wv = w4[u];
            #pragma unroll
            for (int i = 0; i < SEQL; ++i) {
                float4 sv = *(const float4*)&seq[i][u * 4];
                acc[i] += wv.x * sv.x + wv.y * sv.y + wv.z * sv.z + wv.w * sv.w;
            }
        }
        float bias = ab[tid];
        #pragma unroll
        for (int i = 0; i < SEQL; ++i) qkv[i][tid] = acc[i] + bias;
    }
    __syncthreads();

    for (int idx = tid; idx < NH * SEQL * SEQL; idx += 256) {
        int h = idx / (SEQL * SEQL);
        int r = idx % (SEQL * SEQL);
        int i = r / SEQL, j = r % SEQL;
        const float4* qp = (const float4*)&qkv[i][h * HD];
        const float4* kp = (const float4*)&qkv[j][64 + h * HD];
        float s = 0.f;
        #pragma unroll
        for (int u = 0; u < 4; ++u) {
            float4 qv = qp[u], kv = kp[u];
            s += qv.x * kv.x + qv.y * kv.y + qv.z * kv.z + qv.w * kv.w;
        }
        sc[h][i][j] = s * 0.25f;
    }
    __syncthreads();

    if (tid < NH * SEQL) {
        int h = tid / SEQL, i = tid % SEQL;
        float m = -1e30f;
        #pragma unroll
        for (int j = 0; j < SEQL; ++j) m = fmaxf(m, sc[h][i][j]);
        float sum = 0.f;
        #pragma unroll
        for (int j = 0; j < SEQL; ++j) { float e = expf(sc[h][i][j] - m); sc[h][i][j] = e; sum += e; }
        float inv = 1.0f / sum;
        #pragma unroll
        for (int j = 0; j < SEQL; ++j) sc[h][i][j] *= inv;
    }
    __syncthreads();

    for (int idx = tid; idx < SEQL * DL; idx += 256) {
        int i = idx >> 6, d = idx & 63, h = d >> 4;
        float s = 0.f;
        #pragma unroll
        for (int j = 0; j < SEQL; ++j) s += sc[h][i][j] * qkv[j][128 + d];
        ctx[i][d] = s;
    }
    __syncthreads();

    // attn_out + residual: 128 threads, rows split 0-8 / 9-16, full unroll
    if (tid < 128) {
        int d = tid & 63;
        const float4* w4 = (const float4*)(ow + d * DL);
        float bias = ob[d];
        if (tid < 64) {
            float acc[9];
            #pragma unroll
            for (int q = 0; q < 9; ++q) acc[q] = 0.f;
            #pragma unroll
            for (int u = 0; u < 16; ++u) {
                float4 wv = w4[u];
                #pragma unroll
                for (int i = 0; i < 9; ++i) {
                    float4 cv = *(const float4*)&ctx[i][u * 4];
                    acc[i] += wv.x * cv.x + wv.y * cv.y + wv.z * cv.z + wv.w * cv.w;
                }
            }
            #pragma unroll
            for (int i = 0; i < 9; ++i) hb[i][d] = acc[i] + bias + seq[i][d];
        } else {
            float acc[8];
            #pragma unroll
            for (int q = 0; q < 8; ++q) acc[q] = 0.f;
            #pragma unroll
            for (int u = 0; u < 16; ++u) {
                float4 wv = w4[u];
                #pragma unroll
                for (int i = 0; i < 8; ++i) {
                    float4 cv = *(const float4*)&ctx[9 + i][u * 4];
                    acc[i] += wv.x * cv.x + wv.y * cv.y + wv.z * cv.z + wv.w * cv.w;
                }
            }
            #pragma unroll
            for (int i = 0; i < 8; ++i) hb[9 + i][d] = acc[i] + bias + seq[9 + i][d];
        }
    }
    __syncthreads();

    // LN rows 1..16 fused into logit: warp per 2 rows, shuffle reductions
    {
        int w = tid >> 5, lane = tid & 31;
        #pragma unroll
        for (int rr = 0; rr < 2; ++rr) {
            int i = 1 + (w << 1) + rr;
            float v0 = hb[i][lane], v1 = hb[i][lane + 32];
            float mu = wsum(v0 + v1) * (1.0f / DL);
            float d0 = v0 - mu, d1 = v1 - mu;
            float var = wsum(d0 * d0 + d1 * d1) * (1.0f / DL);
            float rstd = rsqrtf(var + 1e-5f);
            float lp = (d0 * rstd * lnw[lane]      + lnb[lane])      * lsw[lane]
                     + (d1 * rstd * lnw[lane + 32] + lnb[lane + 32]) * lsw[lane + 32];
            lp = wsum(lp);
            if (lane == 0) logits[i - 1] = lp + lsb[0] + g_gb[b * NEXP + (i - 1)];
        }
    }
    __syncthreads();

    if (tid == 0) {
        float m = -1e30f;
        #pragma unroll
        for (int e = 0; e < NEXP; ++e) m = fmaxf(m, logits[e]);
        float p[NEXP]; float sum = 0.f;
        #pragma unroll
        for (int e = 0; e < NEXP; ++e) { p[e] = expf(logits[e] - m); sum += p[e]; }
        float inv = 1.0f / sum;
        float best = -1e30f, sec = -1e30f; int bi = 0, si = 0;
        #pragma unroll
        for (int e = 0; e < NEXP; ++e) {
            float pe = p[e] * inv;
            g_probs[n * NEXP + e] = pe;
            if (pe > best)      { sec = best; si = bi; best = pe; bi = e; }
            else if (pe > sec)  { sec = pe; si = e; }
        }
        float s2 = best + sec;
        g_tw[2*n]   = best / s2;
        g_tw[2*n+1] = sec  / s2;
        g_ti[2*n]   = bi;
        g_ti[2*n+1] = si;
        int p0 = atomicAdd(&g_ecnt[bi], 1); g_elist[bi * NTOK + p0] = 2*n;
        int p1 = atomicAdd(&g_ecnt[si], 1); g_elist[si * NTOK + p1] = 2*n + 1;
    }
    __syncthreads();

    // act = gelu(sel) computed ONCE per assignment
    if (tid < 2 * DL) {
        int k = tid >> 6, d = tid & 63;
        int e = g_ti[2*n + k];
        g_act[(size_t)(2*n + k) * DL + d] = gelu_f(g_ef[(size_t)n * 1024 + e * DL + d]);
    }
}

// ---------------- K4: expert up-projection, register-tiled -----------------
// grid (16 experts, 16 m-tiles). Weight tile (wt[d][col], 16KB) loaded ONCE
// per block. acts streamed in 32-slot chunks. Thread tile = 4 slots x 2 cols
// (warp = slot-group, lane = col pair): per d-step, 4 broadcast LDS + 1
// LDS.64 feed 8 FFMA -> smem-byte traffic cut 4x vs scalar version.
// Exactly 2 commutative atomicAdds per out element -> deterministic.
__global__ void __launch_bounds__(256)
k_moe2(const float* __restrict__ w_up, float* __restrict__ out, int has_aux)
{
    __shared__ __align__(16) float wt[DL][64];     // 16 KB, loaded once
    __shared__ __align__(16) float acts[32][64];   // 8 KB per chunk
    __shared__ int slist[32];
    __shared__ float partial[NEXP];
    int tid = threadIdx.x;
    int e  = blockIdx.x;
    int m0 = blockIdx.y * 64;
    int wid = tid >> 5, lane = tid & 31;

    // weight tile: wt[d][col] = w_up[e][d][m0+col]  (coalesced)
    #pragma unroll
    for (int j = 0; j < 16; ++j) {
        int idx = tid + j * 256;
        int d = idx >> 6, cc = idx & 63;
        wt[d][cc] = w_up[(((size_t)e << 6) + d) * 1024 + m0 + cc];
    }
    int cnt = g_ecnt[e];

    for (int base = 0; base < cnt; base += 32) {
        __syncthreads();                         // protect acts/slist reuse (and first-iter wt)
        if (tid < 32) slist[tid] = (base + tid < cnt) ? g_elist[e * NTOK + base + tid] : -1;
        __syncthreads();
        #pragma unroll
        for (int j = 0; j < 8; ++j) {
            int i = tid + j * 256;               // 2048 = 32 slots x 64
            int slot = i >> 6, d = i & 63;
            int a = slist[slot];
            acts[slot][d] = (a >= 0) ? g_act[(size_t)a * DL + d] : 0.f;
        }
        __syncthreads();

        // register-tiled outer product: warp wid -> slots wid*4..+3, lane -> cols lane*2..+1
        float s00 = 0.f, s01 = 0.f, s10 = 0.f, s11 = 0.f;
        float s20 = 0.f, s21 = 0.f, s30 = 0.f, s31 = 0.f;
        const float* a0p = &acts[wid * 4 + 0][0];
        const float* a1p = &acts[wid * 4 + 1][0];
        const float* a2p = &acts[wid * 4 + 2][0];
        const float* a3p = &acts[wid * 4 + 3][0];
        #pragma unroll
        for (int d = 0; d < DL; ++d) {
            float2 wv = *(const float2*)&wt[d][lane * 2];
            float a0 = a0p[d], a1 = a1p[d], a2 = a2p[d], a3 = a3p[d];
            s00 += a0 * wv.x; s01 += a0 * wv.y;
            s10 += a1 * wv.x; s11 += a1 * wv.y;
            s20 += a2 * wv.x; s21 += a2 * wv.y;
            s30 += a3 * wv.x; s31 += a3 * wv.y;
        }
        float rs[4][2] = {{s00, s01}, {s10, s11}, {s20, s21}, {s30, s31}};
        #pragma unroll
        for (int i = 0; i < 4; ++i) {
            int a = slist[wid * 4 + i];
            if (a >= 0) {
                float twv = g_tw[a];
                float* op = &out[(size_t)(a >> 1) * 1024 + m0 + lane * 2];
                atomicAdd(op,     twv * rs[i][0]);
                atomicAdd(op + 1, twv * rs[i][1]);
            }
        }
    }

    // fused aux loss (block 0,0 only; deterministic fixed-order reduction)
    if (has_aux && blockIdx.x == 0 && blockIdx.y == 0) {
        __syncthreads();
        int w = tid >> 5, ln = tid & 31;
        for (int ee = w; ee < NEXP; ee += 8) {
            float psum = 0.f; int ccnt = 0;
            for (int n = ln; n < NTOK; n += 32) {
                psum += g_probs[n * NEXP + ee];
                ccnt += (g_ti[2*n] == ee) + (g_ti[2*n+1] == ee);
            }
            #pragma unroll
            for (int o = 16; o; o >>= 1) {
                psum += __shfl_down_sync(0xffffffffu, psum, o);
                ccnt += __shfl_down_sync(0xffffffffu, ccnt, o);
            }
            if (ln == 0) partial[ee] = psum * (float)ccnt;
        }
        __syncthreads();
        if (tid == 0) {
            float ssum = 0.f;
            #pragma unroll
            for (int q = 0; q < NEXP; ++q) ssum += partial[q];
            out[NTOK * 1024] = ssum * ((float)NEXP / ((float)NTOK * (float)NTOK));
        }
    }
}

// ---------------- launch ---------------------------------------------------
extern "C" void kernel_launch(void* const* d_in, const int* in_sizes, int n_in,
                              void* d_out, int out_size)
{
    const float* x      = (const float*)d_in[0];
    const float* w_down = (const float*)d_in[1];
    const float* pos    = (const float*)d_in[2];
    const float* gp_w   = (const float*)d_in[3];
    const float* gp_b   = (const float*)d_in[4];
    const float* aw     = (const float*)d_in[5];
    const float* ab     = (const float*)d_in[6];
    const float* ow     = (const float*)d_in[7];
    const float* ob     = (const float*)d_in[8];
    const float* lnw    = (const float*)d_in[9];
    const float* lnb    = (const float*)d_in[10];
    const float* lsw    = (const float*)d_in[11];
    const float* lsb    = (const float*)d_in[12];
    const float* g1w    = (const float*)d_in[13];
    const float* g1b    = (const float*)d_in[14];
    const float* g2w    = (const float*)d_in[15];
    const float* g2b    = (const float*)d_in[16];
    const float* wup    = (const float*)d_in[17];
    float* out = (float*)d_out;

    static int attr_done = 0;
    if (!attr_done) {
        cudaFuncSetAttribute(k_ef_mma, cudaFuncAttributeMaxDynamicSharedMemorySize, EF_SMEM);
        attr_done = 1;
    }

    int has_aux = (out_size > NTOK * 1024) ? 1 : 0;

    k_split  <<<2048, 256>>>(x, w_down, out, out_size);
    k_ef_mma <<<516, 128, EF_SMEM>>>(gp_w, gp_b, g1w, g1b, g2w, g2b);
    k_token  <<<NTOK, 256>>>(pos, aw, ab, ow, ob, lnw, lnb, lsw, lsb);
    k_moe2   <<<dim3(NEXP, 16), 256>>>(wup, out, has_aux);
}

// round 15
// speedup vs baseline: 1.2490x; 1.0408x over previous
#include <cuda_runtime.h>
#include <cuda_bf16.h>
#include <math.h>
#include <stdint.h>

// Problem constants
#define BQ   4
#define TQ   256
#define DM   1024
#define NEXP 16
#define DL   64
#define NH   4
#define HD   16
#define NTOK 1024      // B*T
#define SEQL 17        // E+1
#define NASSIGN (NTOK*2)

// ---------------- scratch (device globals; no allocation allowed) ----------
__device__ float g_ef   [NTOK * 1024];
__device__ float g_act  [NASSIGN * DL];
__device__ float g_probs[NTOK * NEXP];
__device__ float g_tw   [NASSIGN];
__device__ int   g_ti   [NASSIGN];
__device__ float g_gctx [BQ * DL];
__device__ float g_gb   [BQ * NEXP];
__device__ int   g_ecnt [NEXP];
__device__ int   g_elist[NEXP * NTOK];
__device__ float g_xmp  [BQ][8][DM];
__device__ __nv_bfloat16 g_xhi[DM * DM];
__device__ __nv_bfloat16 g_xlo[DM * DM];
__device__ __nv_bfloat16 g_whi[DM * DM];
__device__ __nv_bfloat16 g_wlo[DM * DM];

__device__ __forceinline__ float gelu_f(float x) {
    return 0.5f * x * (1.0f + erff(x * 0.70710678118654752440f));
}
__device__ __forceinline__ uint32_t smem_u32(const void* p) {
    return (uint32_t)__cvta_generic_to_shared(p);
}
__device__ __forceinline__ void cp_async8(uint32_t dst, const void* src) {
    asm volatile("cp.async.ca.shared.global [%0], [%1], 8;"
                 :: "r"(dst), "l"(src) : "memory");
}
__device__ __forceinline__ void mma_bf16(float* c, const uint32_t* a,
                                         uint32_t b0, uint32_t b1) {
    asm volatile(
        "mma.sync.aligned.m16n8k16.row.col.f32.bf16.bf16.f32 "
        "{%0,%1,%2,%3}, {%4,%5,%6,%7}, {%8,%9}, {%0,%1,%2,%3};"
        : "+f"(c[0]), "+f"(c[1]), "+f"(c[2]), "+f"(c[3])
        : "r"(a[0]), "r"(a[1]), "r"(a[2]), "r"(a[3]), "r"(b0), "r"(b1));
}
__device__ __forceinline__ void ldsm4(uint32_t* r, uint32_t addr) {
    asm volatile("ldmatrix.sync.aligned.m8n8.x4.shared.b16 {%0,%1,%2,%3}, [%4];"
                 : "=r"(r[0]), "=r"(r[1]), "=r"(r[2]), "=r"(r[3]) : "r"(addr));
}
__device__ __forceinline__ float wsum(float v) {
    #pragma unroll
    for (int o = 16; o; o >>= 1) v += __shfl_xor_sync(0xffffffffu, v, o);
    return v;
}

// ---------------- K0: split X,W to bf16 hi/lo + zero g_ef/out + mean parts -
__global__ void k_split(const float* __restrict__ X, const float* __restrict__ W,
                        float* __restrict__ out, int out_size)
{
    int tid = threadIdx.x;
    int i = blockIdx.x * 256 + tid;
    *(float2*)&g_ef[(size_t)i * 2] = make_float2(0.f, 0.f);
    *(float2*)&out[(size_t)i * 2] = make_float2(0.f, 0.f);
    if (i == 0 && out_size > NTOK * 1024) out[NTOK * 1024] = 0.f;

    const float4* src; __nv_bfloat16 *dh, *dl; int j;
    if (i < 262144) { src = (const float4*)X; dh = g_xhi; dl = g_xlo; j = i; }
    else            { src = (const float4*)W; dh = g_whi; dl = g_wlo; j = i - 262144; }
    float4 v = src[j];
    __nv_bfloat16 h0 = __float2bfloat16(v.x), h1 = __float2bfloat16(v.y);
    __nv_bfloat16 h2 = __float2bfloat16(v.z), h3 = __float2bfloat16(v.w);
    __nv_bfloat16 l0 = __float2bfloat16(v.x - __bfloat162float(h0));
    __nv_bfloat16 l1 = __float2bfloat16(v.y - __bfloat162float(h1));
    __nv_bfloat16 l2 = __float2bfloat16(v.z - __bfloat162float(h2));
    __nv_bfloat16 l3 = __float2bfloat16(v.w - __bfloat162float(h3));
    __nv_bfloat162 hA = __nv_bfloat162(h0, h1), hB = __nv_bfloat162(h2, h3);
    __nv_bfloat162 lA = __nv_bfloat162(l0, l1), lB = __nv_bfloat162(l2, l3);
    uint2 ho, lo;
    ho.x = *(uint32_t*)&hA; ho.y = *(uint32_t*)&hB;
    lo.x = *(uint32_t*)&lA; lo.y = *(uint32_t*)&lB;
    *(uint2*)(dh + (size_t)j * 4) = ho;
    *(uint2*)(dl + (size_t)j * 4) = lo;

    if (blockIdx.x < 32) {
        int b = blockIdx.x >> 3, c = blockIdx.x & 7;
        const float* p0 = X + ((size_t)b * TQ + c * 32) * DM;
        for (int d = tid; d < DM; d += 256) {
            float s = 0.f;
            const float* p = p0 + d;
            #pragma unroll 8
            for (int t = 0; t < 32; ++t) s += p[(size_t)t * DM];
            g_xmp[b][c][d] = s;
        }
    }
}

// ---------------- K2: ef GEMM (blocks 0..511) + global context (512..515) --
#define BK     32
#define TSTR   40
#define KHALF  16
#define EF_TILE   (64 * TSTR)
#define EF_STAGE  (4 * EF_TILE)
#define EF_SMEM   (3 * EF_STAGE * 2)          // 61440 bytes

__global__ void __launch_bounds__(128) k_ef_mma(
    const float* __restrict__ gp_w, const float* __restrict__ gp_b,
    const float* __restrict__ g1_w, const float* __restrict__ g1_b,
    const float* __restrict__ g2_w, const float* __restrict__ g2_b)
{
    extern __shared__ __align__(16) char dsm[];
    int tid = threadIdx.x;

    // ---- fused k_global path (4 blocks) ----
    if (blockIdx.x >= 512) {
        float* xm   = (float*)dsm;
        float* part = xm + DM;
        float* gctx = part + 128;
        float* g1s  = gctx + 64;
        int b = blockIdx.x - 512;
        if (b == 0 && tid < NEXP) g_ecnt[tid] = 0;
        for (int d = tid; d < DM; d += 128) {
            float s = 0.f;
            #pragma unroll
            for (int c = 0; c < 8; ++c) s += g_xmp[b][c][d];
            xm[d] = s * (1.0f / (float)TQ);
        }
        __syncthreads();
        {
            int j = tid >> 1, p = tid & 1;
            float s = 0.f;
            const float* w  = gp_w + (size_t)j * DM + p * 512;
            const float* xp = xm + p * 512;
            #pragma unroll 4
            for (int d = 0; d < 512; ++d) s += xp[d] * w[d];
            part[tid] = s;
        }
        __syncthreads();
        if (tid < DL) {
            float s = part[2*tid] + part[2*tid+1] + gp_b[tid];
            gctx[tid] = s;
            g_gctx[b * DL + tid] = s;
        }
        __syncthreads();
        {
            float s = g1_b[tid];
            const float* w = g1_w + tid * DL;
            #pragma unroll
            for (int d = 0; d < DL; ++d) s += gctx[d] * w[d];
            g1s[tid] = gelu_f(s);
        }
        __syncthreads();
        if (tid < NEXP) {
            float s = g2_b[tid];
            const float* w = g2_w + tid * 128;
            #pragma unroll
            for (int c = 0; c < 128; ++c) s += g1s[c] * w[c];
            g_gb[b * NEXP + tid] = s;
        }
        return;
    }

    // ---- GEMM path ----
    __nv_bfloat16* smb = (__nv_bfloat16*)dsm;
    auto tilep = [&](int s, int t4) { return smb + (s * 4 + t4) * EF_TILE; };

    int wid = tid >> 5, lane = tid & 31;
    int g = lane >> 2, t = lane & 3;
    int wm = (wid & 1) * 32, wn = (wid >> 1) * 32;
    int bx = blockIdx.x;
    int kz = bx >> 8, idx = bx & 255;
    int m0 = (idx >> 4) * 64, n0 = (idx & 15) * 64;
    int kbase = kz * (KHALF * BK);

    int loff = ((lane & 15) * TSTR + (lane >> 4) * 8) * 2;

    const __nv_bfloat16* tsrc[4] = {
        g_xhi + (size_t)m0 * DM + kbase, g_xlo + (size_t)m0 * DM + kbase,
        g_whi + (size_t)n0 * DM + kbase, g_wlo + (size_t)n0 * DM + kbase
    };

    float acc[2][4][4];
    #pragma unroll
    for (int mf = 0; mf < 2; ++mf)
        #pragma unroll
        for (int nf = 0; nf < 4; ++nf)
            #pragma unroll
            for (int q = 0; q < 4; ++q) acc[mf][nf][q] = 0.f;

    auto issue = [&](int c, int s) {
        int k0 = c * BK;
        #pragma unroll
        for (int t4 = 0; t4 < 4; ++t4) {
            const __nv_bfloat16* src = tsrc[t4] + k0;
            __nv_bfloat16* dt = tilep(s, t4);
            #pragma unroll
            for (int jj = 0; jj < 4; ++jj) {
                int u = tid + jj * 128;
                int r = u >> 3, c8 = u & 7;
                cp_async8(smem_u32(dt + r * TSTR + c8 * 4),
                          src + (size_t)r * DM + c8 * 4);
            }
        }
    };

    issue(0, 0); asm volatile("cp.async.commit_group;" ::: "memory");
    issue(1, 1); asm volatile("cp.async.commit_group;" ::: "memory");

    for (int c = 0; c < KHALF; ++c) {
        int bsel = c % 3;
        asm volatile("cp.async.wait_group 1;" ::: "memory");
        __syncthreads();
        if (c + 2 < KHALF) issue(c + 2, (c + 2) % 3);
        asm volatile("cp.async.commit_group;" ::: "memory");

        uint32_t baseAh = smem_u32(tilep(bsel, 0)) + loff;
        uint32_t baseAl = smem_u32(tilep(bsel, 1)) + loff;
        uint32_t baseBh = smem_u32(tilep(bsel, 2)) + loff;
        uint32_t baseBl = smem_u32(tilep(bsel, 3)) + loff;

        uint32_t a0h[2][4], a0l[2][4], b0h[2][4], b0l[2][4];
        uint32_t a1h[2][4], a1l[2][4], b1h[2][4], b1l[2][4];
        #pragma unroll
        for (int mf = 0; mf < 2; ++mf) {
            uint32_t ro = ((wm + mf * 16) * TSTR) * 2;
            ldsm4(a0h[mf], baseAh + ro);        ldsm4(a0l[mf], baseAl + ro);
            ldsm4(a1h[mf], baseAh + ro + 32);   ldsm4(a1l[mf], baseAl + ro + 32);
        }
        #pragma unroll
        for (int G = 0; G < 2; ++G) {
            uint32_t ro = ((wn + G * 16) * TSTR) * 2;
            ldsm4(b0h[G], baseBh + ro);         ldsm4(b0l[G], baseBl + ro);
            ldsm4(b1h[G], baseBh + ro + 32);    ldsm4(b1l[G], baseBl + ro + 32);
        }
        #pragma unroll
        for (int mf = 0; mf < 2; ++mf)
            #pragma unroll
            for (int nf = 0; nf < 4; ++nf) {
                int G = nf >> 1, o = nf & 1;
                mma_bf16(acc[mf][nf], a0h[mf], b0h[G][o], b0h[G][o + 2]);
                mma_bf16(acc[mf][nf], a0h[mf], b0l[G][o], b0l[G][o + 2]);
                mma_bf16(acc[mf][nf], a0l[mf], b0h[G][o], b0h[G][o + 2]);
            }
        #pragma unroll
        for (int mf = 0; mf < 2; ++mf)
            #pragma unroll
            for (int nf = 0; nf < 4; ++nf) {
                int G = nf >> 1, o = nf & 1;
                mma_bf16(acc[mf][nf], a1h[mf], b1h[G][o], b1h[G][o + 2]);
                mma_bf16(acc[mf][nf], a1h[mf], b1l[G][o], b1l[G][o + 2]);
                mma_bf16(acc[mf][nf], a1l[mf], b1h[G][o], b1h[G][o + 2]);
            }
    }

    #pragma unroll
    for (int mf = 0; mf < 2; ++mf) {
        int row = m0 + wm + mf * 16 + g;
        #pragma unroll
        for (int nf = 0; nf < 4; ++nf) {
            int col = n0 + wn + nf * 8 + 2 * t;
            atomicAdd(&g_ef[(size_t)(row    ) * DM + col    ], acc[mf][nf][0]);
            atomicAdd(&g_ef[(size_t)(row    ) * DM + col + 1], acc[mf][nf][1]);
            atomicAdd(&g_ef[(size_t)(row + 8) * DM + col    ], acc[mf][nf][2]);
            atomicAdd(&g_ef[(size_t)(row + 8) * DM + col + 1], acc[mf][nf][3]);
        }
    }
}

// ---------------- K3: per-token micro-transformer + routing ---------------
__global__ void __launch_bounds__(256)
k_token(const float* __restrict__ pos,
        const float* __restrict__ aw, const float* __restrict__ ab,
        const float* __restrict__ ow, const float* __restrict__ ob,
        const float* __restrict__ lnw, const float* __restrict__ lnb,
        const float* __restrict__ lsw, const float* __restrict__ lsb)
{
    __shared__ __align__(16) float seq[SEQL][DL];
    __shared__ __align__(16) float qkv[SEQL][192];
    __shared__ float sc[NH][SEQL][SEQL];
    __shared__ __align__(16) float ctx[SEQL][DL];
    __shared__ __align__(16) float hb[SEQL][DL];
    __shared__ float logits[NEXP];

    int n = blockIdx.x, tid = threadIdx.x;
    int b = n >> 8;

    for (int i = tid; i < NEXP * DL; i += 256)
        seq[1 + (i >> 6)][i & 63] = g_ef[(size_t)n * 1024 + i] + pos[i];
    if (tid < DL) seq[0][tid] = g_gctx[b * DL + tid];
    __syncthreads();

    if (tid < 192) {
        float acc[SEQL];
        #pragma unroll
        for (int i = 0; i < SEQL; ++i) acc[i] = 0.f;
        const float4* w4 = (const float4*)(aw + tid * DL);
        #pragma unroll
        for (int u = 0; u < 16; ++u) {
            float4 wv = w4[u];
            #pragma unroll
            for (int i = 0; i < SEQL; ++i) {
                float4 sv = *(const float4*)&seq[i][u * 4];
                acc[i] += wv.x * sv.x + wv.y * sv.y + wv.z * sv.z + wv.w * sv.w;
            }
        }
        float bias = ab[tid];
        #pragma unroll
        for (int i = 0; i < SEQL; ++i) qkv[i][tid] = acc[i] + bias;
    }
    __syncthreads();

    for (int idx = tid; idx < NH * SEQL * SEQL; idx += 256) {
        int h = idx / (SEQL * SEQL);
        int r = idx % (SEQL * SEQL);
        int i = r / SEQL, j = r % SEQL;
        const float4* qp = (const float4*)&qkv[i][h * HD];
        const float4* kp = (const float4*)&qkv[j][64 + h * HD];
        float s = 0.f;
        #pragma unroll
        for (int u = 0; u < 4; ++u) {
            float4 qv = qp[u], kv = kp[u];
            s += qv.x * kv.x + qv.y * kv.y + qv.z * kv.z + qv.w * kv.w;
        }
        sc[h][i][j] = s * 0.25f;
    }
    __syncthreads();

    if (tid < NH * SEQL) {
        int h = tid / SEQL, i = tid % SEQL;
        float m = -1e30f;
        #pragma unroll
        for (int j = 0; j < SEQL; ++j) m = fmaxf(m, sc[h][i][j]);
        float sum = 0.f;
        #pragma unroll
        for (int j = 0; j < SEQL; ++j) { float e = expf(sc[h][i][j] - m); sc[h][i][j] = e; sum += e; }
        float inv = 1.0f / sum;
        #pragma unroll
        for (int j = 0; j < SEQL; ++j) sc[h][i][j] *= inv;
    }
    __syncthreads();

    for (int idx = tid; idx < SEQL * DL; idx += 256) {
        int i = idx >> 6, d = idx & 63, h = d >> 4;
        float s = 0.f;
        #pragma unroll
        for (int j = 0; j < SEQL; ++j) s += sc[h][i][j] * qkv[j][128 + d];
        ctx[i][d] = s;
    }
    __syncthreads();

    // attn_out + residual: 128 threads, rows split 0-8 / 9-16, full unroll
    if (tid < 128) {
        int d = tid & 63;
        const float4* w4 = (const float4*)(ow + d * DL);
        float bias = ob[d];
        if (tid < 64) {
            float acc[9];
            #pragma unroll
            for (int q = 0; q < 9; ++q) acc[q] = 0.f;
            #pragma unroll
            for (int u = 0; u < 16; ++u) {
                float4 wv = w4[u];
                #pragma unroll
                for (int i = 0; i < 9; ++i) {
                    float4 cv = *(const float4*)&ctx[i][u * 4];
                    acc[i] += wv.x * cv.x + wv.y * cv.y + wv.z * cv.z + wv.w * cv.w;
                }
            }
            #pragma unroll
            for (int i = 0; i < 9; ++i) hb[i][d] = acc[i] + bias + seq[i][d];
        } else {
            float acc[8];
            #pragma unroll
            for (int q = 0; q < 8; ++q) acc[q] = 0.f;
            #pragma unroll
            for (int u = 0; u < 16; ++u) {
                float4 wv = w4[u];
                #pragma unroll
                for (int i = 0; i < 8; ++i) {
                    float4 cv = *(const float4*)&ctx[9 + i][u * 4];
                    acc[i] += wv.x * cv.x + wv.y * cv.y + wv.z * cv.z + wv.w * cv.w;
                }
            }
            #pragma unroll
            for (int i = 0; i < 8; ++i) hb[9 + i][d] = acc[i] + bias + seq[9 + i][d];
        }
    }
    __syncthreads();

    // LN rows 1..16 fused into logit: warp per 2 rows, shuffle reductions
    {
        int w = tid >> 5, lane = tid & 31;
        #pragma unroll
        for (int rr = 0; rr < 2; ++rr) {
            int i = 1 + (w << 1) + rr;
            float v0 = hb[i][lane], v1 = hb[i][lane + 32];
            float mu = wsum(v0 + v1) * (1.0f / DL);
            float d0 = v0 - mu, d1 = v1 - mu;
            float var = wsum(d0 * d0 + d1 * d1) * (1.0f / DL);
            float rstd = rsqrtf(var + 1e-5f);
            float lp = (d0 * rstd * lnw[lane]      + lnb[lane])      * lsw[lane]
                     + (d1 * rstd * lnw[lane + 32] + lnb[lane + 32]) * lsw[lane + 32];
            lp = wsum(lp);
            if (lane == 0) logits[i - 1] = lp + lsb[0] + g_gb[b * NEXP + (i - 1)];
        }
    }
    __syncthreads();

    if (tid == 0) {
        float m = -1e30f;
        #pragma unroll
        for (int e = 0; e < NEXP; ++e) m = fmaxf(m, logits[e]);
        float p[NEXP]; float sum = 0.f;
        #pragma unroll
        for (int e = 0; e < NEXP; ++e) { p[e] = expf(logits[e] - m); sum += p[e]; }
        float inv = 1.0f / sum;
        float best = -1e30f, sec = -1e30f; int bi = 0, si = 0;
        #pragma unroll
        for (int e = 0; e < NEXP; ++e) {
            float pe = p[e] * inv;
            g_probs[n * NEXP + e] = pe;
            if (pe > best)      { sec = best; si = bi; best = pe; bi = e; }
            else if (pe > sec)  { sec = pe; si = e; }
        }
        float s2 = best + sec;
        g_tw[2*n]   = best / s2;
        g_tw[2*n+1] = sec  / s2;
        g_ti[2*n]   = bi;
        g_ti[2*n+1] = si;
        int p0 = atomicAdd(&g_ecnt[bi], 1); g_elist[bi * NTOK + p0] = 2*n;
        int p1 = atomicAdd(&g_ecnt[si], 1); g_elist[si * NTOK + p1] = 2*n + 1;
    }
    __syncthreads();

    // act = gelu(sel) computed ONCE per assignment
    if (tid < 2 * DL) {
        int k = tid >> 6, d = tid & 63;
        int e = g_ti[2*n + k];
        g_act[(size_t)(2*n + k) * DL + d] = gelu_f(g_ef[(size_t)n * 1024 + e * DL + d]);
    }
}

// ---------------- K4: expert up-projection, parallel + register-tiled ------
// grid (NASSIGN/32 = 64 slot-blocks, 16 m-tiles) = 1024 CTAs. Per block:
// 32 sorted slots, acts loaded ONCE; per expert-segment the wt tile is
// (re)loaded and 8 warps compute a 4-slot x 2-col register tile (4 broadcast
// LDS + 1 LDS.64 -> 8 FFMA per d). Boundary warps recompute out-of-segment
// slots but store only in-segment ones -> each out element still gets exactly
// 2 commutative atomicAdds -> deterministic.
#define MSLOT 32
__global__ void __launch_bounds__(256)
k_moe2(const float* __restrict__ w_up, float* __restrict__ out, int has_aux)
{
    __shared__ __align__(16) float wt[DL][64];      // 16 KB
    __shared__ __align__(16) float acts[MSLOT][64]; // 8 KB
    __shared__ int sa[MSLOT];
    __shared__ int se[MSLOT];
    __shared__ int pre[NEXP];
    __shared__ float partial[NEXP];
    int tid = threadIdx.x;
    int base = blockIdx.x * MSLOT;
    int m0 = blockIdx.y * 64;
    int wid = tid >> 5, lane = tid & 31;

    if (tid < NEXP) {
        int o = 0;
        for (int i = 0; i < tid; ++i) o += g_ecnt[i];
        pre[tid] = o;
    }
    __syncthreads();
    if (tid < MSLOT) {
        int f = base + tid;
        int e = 15;
        #pragma unroll
        for (int q = 15; q > 0; --q) if (f < pre[q]) e = q - 1;
        sa[tid] = g_elist[e * NTOK + (f - pre[e])];
        se[tid] = e;
    }
    __syncthreads();
    // acts: 32 slots x 64, loaded once
    #pragma unroll
    for (int j = 0; j < 8; ++j) {
        int i = tid + j * 256;
        int slot = i >> 6, d = i & 63;
        acts[slot][d] = g_act[(size_t)sa[slot] * DL + d];
    }

    int s = 0;
    while (s < MSLOT) {
        int e = se[s];
        int r = s + 1;
        while (r < MSLOT && se[r] == e) ++r;
        __syncthreads();                        // protect wt reuse (and first-iter acts)
        #pragma unroll
        for (int j = 0; j < 16; ++j) {
            int idx = tid + j * 256;
            int d = idx >> 6, cc = idx & 63;
            wt[d][cc] = w_up[(((size_t)e << 6) + d) * 1024 + m0 + cc];
        }
        __syncthreads();

        int w0 = wid * 4;
        if (w0 < r && w0 + 4 > s) {             // warp overlaps segment
            float s00 = 0.f, s01 = 0.f, s10 = 0.f, s11 = 0.f;
            float s20 = 0.f, s21 = 0.f, s30 = 0.f, s31 = 0.f;
            const float* a0p = &acts[w0 + 0][0];
            const float* a1p = &acts[w0 + 1][0];
            const float* a2p = &acts[w0 + 2][0];
            const float* a3p = &acts[w0 + 3][0];
            #pragma unroll
            for (int d = 0; d < DL; ++d) {
                float2 wv = *(const float2*)&wt[d][lane * 2];
                float a0 = a0p[d], a1 = a1p[d], a2 = a2p[d], a3 = a3p[d];
                s00 += a0 * wv.x; s01 += a0 * wv.y;
                s10 += a1 * wv.x; s11 += a1 * wv.y;
                s20 += a2 * wv.x; s21 += a2 * wv.y;
                s30 += a3 * wv.x; s31 += a3 * wv.y;
            }
            float rs[4][2] = {{s00, s01}, {s10, s11}, {s20, s21}, {s30, s31}};
            #pragma unroll
            for (int i = 0; i < 4; ++i) {
                int slot = w0 + i;
                if (slot >= s && slot < r) {
                    int a = sa[slot];
                    float twv = g_tw[a];
                    float* op = &out[(size_t)(a >> 1) * 1024 + m0 + lane * 2];
                    atomicAdd(op,     twv * rs[i][0]);
                    atomicAdd(op + 1, twv * rs[i][1]);
                }
            }
        }
        s = r;
    }

    // fused aux loss (block 0,0 only; deterministic fixed-order reduction)
    if (has_aux && blockIdx.x == 0 && blockIdx.y == 0) {
        __syncthreads();
        int w = tid >> 5, ln = tid & 31;
        for (int ee = w; ee < NEXP; ee += 8) {
            float psum = 0.f; int ccnt = 0;
            for (int n = ln; n < NTOK; n += 32) {
                psum += g_probs[n * NEXP + ee];
                ccnt += (g_ti[2*n] == ee) + (g_ti[2*n+1] == ee);
            }
            #pragma unroll
            for (int o = 16; o; o >>= 1) {
                psum += __shfl_down_sync(0xffffffffu, psum, o);
                ccnt += __shfl_down_sync(0xffffffffu, ccnt, o);
            }
            if (ln == 0) partial[ee] = psum * (float)ccnt;
        }
        __syncthreads();
        if (tid == 0) {
            float ssum = 0.f;
            #pragma unroll
            for (int q = 0; q < NEXP; ++q) ssum += partial[q];
            out[NTOK * 1024] = ssum * ((float)NEXP / ((float)NTOK * (float)NTOK));
        }
    }
}

// ---------------- launch ---------------------------------------------------
extern "C" void kernel_launch(void* const* d_in, const int* in_sizes, int n_in,
                              void* d_out, int out_size)
{
    const float* x      = (const float*)d_in[0];
    const float* w_down = (const float*)d_in[1];
    const float* pos    = (const float*)d_in[2];
    const float* gp_w   = (const float*)d_in[3];
    const float* gp_b   = (const float*)d_in[4];
    const float* aw     = (const float*)d_in[5];
    const float* ab     = (const float*)d_in[6];
    const float* ow     = (const float*)d_in[7];
    const float* ob     = (const float*)d_in[8];
    const float* lnw    = (const float*)d_in[9];
    const float* lnb    = (const float*)d_in[10];
    const float* lsw    = (const float*)d_in[11];
    const float* lsb    = (const float*)d_in[12];
    const float* g1w    = (const float*)d_in[13];
    const float* g1b    = (const float*)d_in[14];
    const float* g2w    = (const float*)d_in[15];
    const float* g2b    = (const float*)d_in[16];
    const float* wup    = (const float*)d_in[17];
    float* out = (float*)d_out;

    static int attr_done = 0;
    if (!attr_done) {
        cudaFuncSetAttribute(k_ef_mma, cudaFuncAttributeMaxDynamicSharedMemorySize, EF_SMEM);
        attr_done = 1;
    }

    int has_aux = (out_size > NTOK * 1024) ? 1 : 0;

    k_split  <<<2048, 256>>>(x, w_down, out, out_size);
    k_ef_mma <<<516, 128, EF_SMEM>>>(gp_w, gp_b, g1w, g1b, g2w, g2b);
    k_token  <<<NTOK, 256>>>(pos, aw, ab, ow, ob, lnw, lnb, lsw, lsb);
    k_moe2   <<<dim3(NASSIGN / MSLOT, 16), 256>>>(wup, out, has_aux);
}

// round 16
// speedup vs baseline: 1.3008x; 1.0415x over previous
#include <cuda_runtime.h>
#include <cuda_bf16.h>
#include <math.h>
#include <stdint.h>

// Problem constants
#define BQ   4
#define TQ   256
#define DM   1024
#define NEXP 16
#define DL   64
#define NH   4
#define HD   16
#define NTOK 1024      // B*T
#define SEQL 17        // E+1
#define NASSIGN (NTOK*2)

// ---------------- scratch (device globals; no allocation allowed) ----------
__device__ float g_ef   [NTOK * 1024];        // kz=0 partial
__device__ float g_ef1  [NTOK * 1024];        // kz=1 partial
__device__ float g_act  [NASSIGN * DL];
__device__ float g_probs[NTOK * NEXP];
__device__ float g_tw   [NASSIGN];
__device__ int   g_ti   [NASSIGN];
__device__ float g_gctx [BQ * DL];
__device__ float g_gb   [BQ * NEXP];
__device__ int   g_ecnt [NEXP];
__device__ int   g_elist[NEXP * NTOK];
__device__ float g_xmp  [BQ][8][DM];
__device__ __nv_bfloat16 g_xhi[DM * DM];
__device__ __nv_bfloat16 g_xlo[DM * DM];
__device__ __nv_bfloat16 g_whi[DM * DM];
__device__ __nv_bfloat16 g_wlo[DM * DM];

__device__ __forceinline__ float gelu_f(float x) {
    return 0.5f * x * (1.0f + erff(x * 0.70710678118654752440f));
}
__device__ __forceinline__ uint32_t smem_u32(const void* p) {
    return (uint32_t)__cvta_generic_to_shared(p);
}
__device__ __forceinline__ void cp_async8(uint32_t dst, const void* src) {
    asm volatile("cp.async.ca.shared.global [%0], [%1], 8;"
                 :: "r"(dst), "l"(src) : "memory");
}
__device__ __forceinline__ void mma_bf16(float* c, const uint32_t* a,
                                         uint32_t b0, uint32_t b1) {
    asm volatile(
        "mma.sync.aligned.m16n8k16.row.col.f32.bf16.bf16.f32 "
        "{%0,%1,%2,%3}, {%4,%5,%6,%7}, {%8,%9}, {%0,%1,%2,%3};"
        : "+f"(c[0]), "+f"(c[1]), "+f"(c[2]), "+f"(c[3])
        : "r"(a[0]), "r"(a[1]), "r"(a[2]), "r"(a[3]), "r"(b0), "r"(b1));
}
__device__ __forceinline__ void ldsm4(uint32_t* r, uint32_t addr) {
    asm volatile("ldmatrix.sync.aligned.m8n8.x4.shared.b16 {%0,%1,%2,%3}, [%4];"
                 : "=r"(r[0]), "=r"(r[1]), "=r"(r[2]), "=r"(r[3]) : "r"(addr));
}
__device__ __forceinline__ float wsum(float v) {
    #pragma unroll
    for (int o = 16; o; o >>= 1) v += __shfl_xor_sync(0xffffffffu, v, o);
    return v;
}

// ---------------- K0: split X,W to bf16 hi/lo + zero out + mean parts ------
__global__ void k_split(const float* __restrict__ X, const float* __restrict__ W,
                        float* __restrict__ out, int out_size)
{
    int tid = threadIdx.x;
    int i = blockIdx.x * 256 + tid;
    // zero output (k_moe2 atomically accumulates into it)
    *(float2*)&out[(size_t)i * 2] = make_float2(0.f, 0.f);

    const float4* src; __nv_bfloat16 *dh, *dl; int j;
    if (i < 262144) { src = (const float4*)X; dh = g_xhi; dl = g_xlo; j = i; }
    else            { src = (const float4*)W; dh = g_whi; dl = g_wlo; j = i - 262144; }
    float4 v = src[j];
    __nv_bfloat16 h0 = __float2bfloat16(v.x), h1 = __float2bfloat16(v.y);
    __nv_bfloat16 h2 = __float2bfloat16(v.z), h3 = __float2bfloat16(v.w);
    __nv_bfloat16 l0 = __float2bfloat16(v.x - __bfloat162float(h0));
    __nv_bfloat16 l1 = __float2bfloat16(v.y - __bfloat162float(h1));
    __nv_bfloat16 l2 = __float2bfloat16(v.z - __bfloat162float(h2));
    __nv_bfloat16 l3 = __float2bfloat16(v.w - __bfloat162float(h3));
    __nv_bfloat162 hA = __nv_bfloat162(h0, h1), hB = __nv_bfloat162(h2, h3);
    __nv_bfloat162 lA = __nv_bfloat162(l0, l1), lB = __nv_bfloat162(l2, l3);
    uint2 ho, lo;
    ho.x = *(uint32_t*)&hA; ho.y = *(uint32_t*)&hB;
    lo.x = *(uint32_t*)&lA; lo.y = *(uint32_t*)&lB;
    *(uint2*)(dh + (size_t)j * 4) = ho;
    *(uint2*)(dl + (size_t)j * 4) = lo;

    if (blockIdx.x < 32) {
        int b = blockIdx.x >> 3, c = blockIdx.x & 7;
        const float* p0 = X + ((size_t)b * TQ + c * 32) * DM;
        for (int d = tid; d < DM; d += 256) {
            float s = 0.f;
            const float* p = p0 + d;
            #pragma unroll 8
            for (int t = 0; t < 32; ++t) s += p[(size_t)t * DM];
            g_xmp[b][c][d] = s;
        }
    }
}

// ---------------- K2: ef GEMM (blocks 0..511) + global context (512..515) --
#define BK     32
#define TSTR   40
#define KHALF  16
#define EF_TILE   (64 * TSTR)
#define EF_STAGE  (4 * EF_TILE)
#define EF_SMEM   (3 * EF_STAGE * 2)          // 61440 bytes

__global__ void __launch_bounds__(128) k_ef_mma(
    const float* __restrict__ gp_w, const float* __restrict__ gp_b,
    const float* __restrict__ g1_w, const float* __restrict__ g1_b,
    const float* __restrict__ g2_w, const float* __restrict__ g2_b)
{
    extern __shared__ __align__(16) char dsm[];
    int tid = threadIdx.x;

    // ---- fused k_global path (4 blocks) ----
    if (blockIdx.x >= 512) {
        float* xm   = (float*)dsm;
        float* part = xm + DM;
        float* gctx = part + 128;
        float* g1s  = gctx + 64;
        int b = blockIdx.x - 512;
        if (b == 0 && tid < NEXP) g_ecnt[tid] = 0;
        for (int d = tid; d < DM; d += 128) {
            float s = 0.f;
            #pragma unroll
            for (int c = 0; c < 8; ++c) s += g_xmp[b][c][d];
            xm[d] = s * (1.0f / (float)TQ);
        }
        __syncthreads();
        {
            int j = tid >> 1, p = tid & 1;
            float s = 0.f;
            const float* w  = gp_w + (size_t)j * DM + p * 512;
            const float* xp = xm + p * 512;
            #pragma unroll 4
            for (int d = 0; d < 512; ++d) s += xp[d] * w[d];
            part[tid] = s;
        }
        __syncthreads();
        if (tid < DL) {
            float s = part[2*tid] + part[2*tid+1] + gp_b[tid];
            gctx[tid] = s;
            g_gctx[b * DL + tid] = s;
        }
        __syncthreads();
        {
            float s = g1_b[tid];
            const float* w = g1_w + tid * DL;
            #pragma unroll
            for (int d = 0; d < DL; ++d) s += gctx[d] * w[d];
            g1s[tid] = gelu_f(s);
        }
        __syncthreads();
        if (tid < NEXP) {
            float s = g2_b[tid];
            const float* w = g2_w + tid * 128;
            #pragma unroll
            for (int c = 0; c < 128; ++c) s += g1s[c] * w[c];
            g_gb[b * NEXP + tid] = s;
        }
        return;
    }

    // ---- GEMM path ----
    __nv_bfloat16* smb = (__nv_bfloat16*)dsm;
    auto tilep = [&](int s, int t4) { return smb + (s * 4 + t4) * EF_TILE; };

    int wid = tid >> 5, lane = tid & 31;
    int g = lane >> 2, t = lane & 3;
    int wm = (wid & 1) * 32, wn = (wid >> 1) * 32;
    int bx = blockIdx.x;
    int kz = bx >> 8, idx = bx & 255;
    int m0 = (idx >> 4) * 64, n0 = (idx & 15) * 64;
    int kbase = kz * (KHALF * BK);

    int loff = ((lane & 15) * TSTR + (lane >> 4) * 8) * 2;

    const __nv_bfloat16* tsrc[4] = {
        g_xhi + (size_t)m0 * DM + kbase, g_xlo + (size_t)m0 * DM + kbase,
        g_whi + (size_t)n0 * DM + kbase, g_wlo + (size_t)n0 * DM + kbase
    };

    float acc[2][4][4];
    #pragma unroll
    for (int mf = 0; mf < 2; ++mf)
        #pragma unroll
        for (int nf = 0; nf < 4; ++nf)
            #pragma unroll
            for (int q = 0; q < 4; ++q) acc[mf][nf][q] = 0.f;

    auto issue = [&](int c, int s) {
        int k0 = c * BK;
        #pragma unroll
        for (int t4 = 0; t4 < 4; ++t4) {
            const __nv_bfloat16* src = tsrc[t4] + k0;
            __nv_bfloat16* dt = tilep(s, t4);
            #pragma unroll
            for (int jj = 0; jj < 4; ++jj) {
                int u = tid + jj * 128;
                int r = u >> 3, c8 = u & 7;
                cp_async8(smem_u32(dt + r * TSTR + c8 * 4),
                          src + (size_t)r * DM + c8 * 4);
            }
        }
    };

    issue(0, 0); asm volatile("cp.async.commit_group;" ::: "memory");
    issue(1, 1); asm volatile("cp.async.commit_group;" ::: "memory");

    for (int c = 0; c < KHALF; ++c) {
        int bsel = c % 3;
        asm volatile("cp.async.wait_group 1;" ::: "memory");
        __syncthreads();
        if (c + 2 < KHALF) issue(c + 2, (c + 2) % 3);
        asm volatile("cp.async.commit_group;" ::: "memory");

        uint32_t baseAh = smem_u32(tilep(bsel, 0)) + loff;
        uint32_t baseAl = smem_u32(tilep(bsel, 1)) + loff;
        uint32_t baseBh = smem_u32(tilep(bsel, 2)) + loff;
        uint32_t baseBl = smem_u32(tilep(bsel, 3)) + loff;

        uint32_t a0h[2][4], a0l[2][4], b0h[2][4], b0l[2][4];
        uint32_t a1h[2][4], a1l[2][4], b1h[2][4], b1l[2][4];
        #pragma unroll
        for (int mf = 0; mf < 2; ++mf) {
            uint32_t ro = ((wm + mf * 16) * TSTR) * 2;
            ldsm4(a0h[mf], baseAh + ro);        ldsm4(a0l[mf], baseAl + ro);
            ldsm4(a1h[mf], baseAh + ro + 32);   ldsm4(a1l[mf], baseAl + ro + 32);
        }
        #pragma unroll
        for (int G = 0; G < 2; ++G) {
            uint32_t ro = ((wn + G * 16) * TSTR) * 2;
            ldsm4(b0h[G], baseBh + ro);         ldsm4(b0l[G], baseBl + ro);
            ldsm4(b1h[G], baseBh + ro + 32);    ldsm4(b1l[G], baseBl + ro + 32);
        }
        #pragma unroll
        for (int mf = 0; mf < 2; ++mf)
            #pragma unroll
            for (int nf = 0; nf < 4; ++nf) {
                int G = nf >> 1, o = nf & 1;
                mma_bf16(acc[mf][nf], a0h[mf], b0h[G][o], b0h[G][o + 2]);
                mma_bf16(acc[mf][nf], a0h[mf], b0l[G][o], b0l[G][o + 2]);
                mma_bf16(acc[mf][nf], a0l[mf], b0h[G][o], b0h[G][o + 2]);
            }
        #pragma unroll
        for (int mf = 0; mf < 2; ++mf)
            #pragma unroll
            for (int nf = 0; nf < 4; ++nf) {
                int G = nf >> 1, o = nf & 1;
                mma_bf16(acc[mf][nf], a1h[mf], b1h[G][o], b1h[G][o + 2]);
                mma_bf16(acc[mf][nf], a1h[mf], b1l[G][o], b1l[G][o + 2]);
                mma_bf16(acc[mf][nf], a1l[mf], b1h[G][o], b1h[G][o + 2]);
            }
    }

    // plain-store epilogue: each kz half owns its buffer (no atomics, no zeroing)
    float* dst = (kz == 0) ? g_ef : g_ef1;
    #pragma unroll
    for (int mf = 0; mf < 2; ++mf) {
        int row = m0 + wm + mf * 16 + g;
        #pragma unroll
        for (int nf = 0; nf < 4; ++nf) {
            int col = n0 + wn + nf * 8 + 2 * t;
            *(float2*)&dst[(size_t)(row    ) * DM + col] = make_float2(acc[mf][nf][0], acc[mf][nf][1]);
            *(float2*)&dst[(size_t)(row + 8) * DM + col] = make_float2(acc[mf][nf][2], acc[mf][nf][3]);
        }
    }
}

// ---------------- K3: per-token micro-transformer + routing ---------------
__global__ void __launch_bounds__(256)
k_token(const float* __restrict__ pos,
        const float* __restrict__ aw, const float* __restrict__ ab,
        const float* __restrict__ ow, const float* __restrict__ ob,
        const float* __restrict__ lnw, const float* __restrict__ lnb,
        const float* __restrict__ lsw, const float* __restrict__ lsb)
{
    __shared__ __align__(16) float seq[SEQL][DL];
    __shared__ __align__(16) float qkv[SEQL][192];
    __shared__ float sc[NH][SEQL][SEQL];
    __shared__ __align__(16) float ctx[SEQL][DL];
    __shared__ __align__(16) float hb[SEQL][DL];
    __shared__ float logits[NEXP];

    int n = blockIdx.x, tid = threadIdx.x;
    int b = n >> 8;

    for (int i = tid; i < NEXP * DL; i += 256)
        seq[1 + (i >> 6)][i & 63] = g_ef[(size_t)n * 1024 + i] + g_ef1[(size_t)n * 1024 + i] + pos[i];
    if (tid < DL) seq[0][tid] = g_gctx[b * DL + tid];
    __syncthreads();

    if (tid < 192) {
        float acc[SEQL];
        #pragma unroll
        for (int i = 0; i < SEQL; ++i) acc[i] = 0.f;
        const float4* w4 = (const float4*)(aw + tid * DL);
        #pragma unroll
        for (int u = 0; u < 16; ++u) {
            float4 wv = w4[u];
            #pragma unroll
            for (int i = 0; i < SEQL; ++i) {
                float4 sv = *(const float4*)&seq[i][u * 4];
                acc[i] += wv.x * sv.x + wv.y * sv.y + wv.z * sv.z + wv.w * sv.w;
            }
        }
        float bias = ab[tid];
        #pragma unroll
        for (int i = 0; i < SEQL; ++i) qkv[i][tid] = acc[i] + bias;
    }
    __syncthreads();

    for (int idx = tid; idx < NH * SEQL * SEQL; idx += 256) {
        int h = idx / (SEQL * SEQL);
        int r = idx % (SEQL * SEQL);
        int i = r / SEQL, j = r % SEQL;
        const float4* qp = (const float4*)&qkv[i][h * HD];
        const float4* kp = (const float4*)&qkv[j][64 + h * HD];
        float s = 0.f;
        #pragma unroll
        for (int u = 0; u < 4; ++u) {
            float4 qv = qp[u], kv = kp[u];
            s += qv.x * kv.x + qv.y * kv.y + qv.z * kv.z + qv.w * kv.w;
        }
        sc[h][i][j] = s * 0.25f;
    }
    __syncthreads();

    if (tid < NH * SEQL) {
        int h = tid / SEQL, i = tid % SEQL;
        float m = -1e30f;
        #pragma unroll
        for (int j = 0; j < SEQL; ++j) m = fmaxf(m, sc[h][i][j]);
        float sum = 0.f;
        #pragma unroll
        for (int j = 0; j < SEQL; ++j) { float e = expf(sc[h][i][j] - m); sc[h][i][j] = e; sum += e; }
        float inv = 1.0f / sum;
        #pragma unroll
        for (int j = 0; j < SEQL; ++j) sc[h][i][j] *= inv;
    }
    __syncthreads();

    for (int idx = tid; idx < SEQL * DL; idx += 256) {
        int i = idx >> 6, d = idx & 63, h = d >> 4;
        float s = 0.f;
        #pragma unroll
        for (int j = 0; j < SEQL; ++j) s += sc[h][i][j] * qkv[j][128 + d];
        ctx[i][d] = s;
    }
    __syncthreads();

    // attn_out + residual: 128 threads, rows split 0-8 / 9-16, full unroll
    if (tid < 128) {
        int d = tid & 63;
        const float4* w4 = (const float4*)(ow + d * DL);
        float bias = ob[d];
        if (tid < 64) {
            float acc[9];
            #pragma unroll
            for (int q = 0; q < 9; ++q) acc[q] = 0.f;
            #pragma unroll
            for (int u = 0; u < 16; ++u) {
                float4 wv = w4[u];
                #pragma unroll
                for (int i = 0; i < 9; ++i) {
                    float4 cv = *(const float4*)&ctx[i][u * 4];
                    acc[i] += wv.x * cv.x + wv.y * cv.y + wv.z * cv.z + wv.w * cv.w;
                }
            }
            #pragma unroll
            for (int i = 0; i < 9; ++i) hb[i][d] = acc[i] + bias + seq[i][d];
        } else {
            float acc[8];
            #pragma unroll
            for (int q = 0; q < 8; ++q) acc[q] = 0.f;
            #pragma unroll
            for (int u = 0; u < 16; ++u) {
                float4 wv = w4[u];
                #pragma unroll
                for (int i = 0; i < 8; ++i) {
                    float4 cv = *(const float4*)&ctx[9 + i][u * 4];
                    acc[i] += wv.x * cv.x + wv.y * cv.y + wv.z * cv.z + wv.w * cv.w;
                }
            }
            #pragma unroll
            for (int i = 0; i < 8; ++i) hb[9 + i][d] = acc[i] + bias + seq[9 + i][d];
        }
    }
    __syncthreads();

    // LN rows 1..16 fused into logit: warp per 2 rows, shuffle reductions
    {
        int w = tid >> 5, lane = tid & 31;
        #pragma unroll
        for (int rr = 0; rr < 2; ++rr) {
            int i = 1 + (w << 1) + rr;
            float v0 = hb[i][lane], v1 = hb[i][lane + 32];
            float mu = wsum(v0 + v1) * (1.0f / DL);
            float d0 = v0 - mu, d1 = v1 - mu;
            float var = wsum(d0 * d0 + d1 * d1) * (1.0f / DL);
            float rstd = rsqrtf(var + 1e-5f);
            float lp = (d0 * rstd * lnw[lane]      + lnb[lane])      * lsw[lane]
                     + (d1 * rstd * lnw[lane + 32] + lnb[lane + 32]) * lsw[lane + 32];
            lp = wsum(lp);
            if (lane == 0) logits[i - 1] = lp + lsb[0] + g_gb[b * NEXP + (i - 1)];
        }
    }
    __syncthreads();

    if (tid == 0) {
        float m = -1e30f;
        #pragma unroll
        for (int e = 0; e < NEXP; ++e) m = fmaxf(m, logits[e]);
        float p[NEXP]; float sum = 0.f;
        #pragma unroll
        for (int e = 0; e < NEXP; ++e) { p[e] = expf(logits[e] - m); sum += p[e]; }
        float inv = 1.0f / sum;
        float best = -1e30f, sec = -1e30f; int bi = 0, si = 0;
        #pragma unroll
        for (int e = 0; e < NEXP; ++e) {
            float pe = p[e] * inv;
            g_probs[n * NEXP + e] = pe;
            if (pe > best)      { sec = best; si = bi; best = pe; bi = e; }
            else if (pe > sec)  { sec = pe; si = e; }
        }
        float s2 = best + sec;
        g_tw[2*n]   = best / s2;
        g_tw[2*n+1] = sec  / s2;
        g_ti[2*n]   = bi;
        g_ti[2*n+1] = si;
        int p0 = atomicAdd(&g_ecnt[bi], 1); g_elist[bi * NTOK + p0] = 2*n;
        int p1 = atomicAdd(&g_ecnt[si], 1); g_elist[si * NTOK + p1] = 2*n + 1;
    }
    __syncthreads();

    // act = gelu(sel) computed ONCE per assignment
    if (tid < 2 * DL) {
        int k = tid >> 6, d = tid & 63;
        int e = g_ti[2*n + k];
        size_t off = (size_t)n * 1024 + e * DL + d;
        g_act[(size_t)(2*n + k) * DL + d] = gelu_f(g_ef[off] + g_ef1[off]);
    }
}

// ---------------- K4: expert up-projection, 2 m-tiles per block ------------
// grid (NASSIGN/32 = 64 slot-blocks, 8 m-tiles of 128 cols) = 512 CTAs
// (single resident wave). Per block: 32 sorted slots, acts loaded once; per
// expert-segment a 64x128 wt tile is loaded and 8 warps compute a
// 4-slot x (2+2)-col register tile. Boundary warps recompute but store only
// in-segment slots -> exactly 2 commutative atomicAdds per out element.
#define MSLOT 32
__global__ void __launch_bounds__(256)
k_moe2(const float* __restrict__ w_up, float* __restrict__ out, int has_aux)
{
    __shared__ __align__(16) float wt[DL][128];     // 32 KB
    __shared__ __align__(16) float acts[MSLOT][64]; // 8 KB
    __shared__ int sa[MSLOT];
    __shared__ int se[MSLOT];
    __shared__ int pre[NEXP];
    __shared__ float partial[NEXP];
    int tid = threadIdx.x;
    int base = blockIdx.x * MSLOT;
    int m0 = blockIdx.y * 128;
    int wid = tid >> 5, lane = tid & 31;

    if (tid < NEXP) {
        int o = 0;
        for (int i = 0; i < tid; ++i) o += g_ecnt[i];
        pre[tid] = o;
    }
    __syncthreads();
    if (tid < MSLOT) {
        int f = base + tid;
        int e = 15;
        #pragma unroll
        for (int q = 15; q > 0; --q) if (f < pre[q]) e = q - 1;
        sa[tid] = g_elist[e * NTOK + (f - pre[e])];
        se[tid] = e;
    }
    __syncthreads();
    #pragma unroll
    for (int j = 0; j < 8; ++j) {
        int i = tid + j * 256;
        int slot = i >> 6, d = i & 63;
        acts[slot][d] = g_act[(size_t)sa[slot] * DL + d];
    }

    int s = 0;
    while (s < MSLOT) {
        int e = se[s];
        int r = s + 1;
        while (r < MSLOT && se[r] == e) ++r;
        __syncthreads();                        // protect wt reuse (and first-iter acts)
        #pragma unroll
        for (int j = 0; j < 32; ++j) {
            int idx = tid + j * 256;            // 8192 = 64 x 128
            int d = idx >> 7, cc = idx & 127;
            wt[d][cc] = w_up[(((size_t)e << 6) + d) * 1024 + m0 + cc];
        }
        __syncthreads();

        int w0 = wid * 4;
        if (w0 < r && w0 + 4 > s) {             // warp overlaps segment
            float sA[4][2] = {{0,0},{0,0},{0,0},{0,0}};  // cols lane*2, lane*2+1
            float sB[4][2] = {{0,0},{0,0},{0,0},{0,0}};  // cols 64+lane*2, 64+lane*2+1
            const float* a0p = &acts[w0 + 0][0];
            const float* a1p = &acts[w0 + 1][0];
            const float* a2p = &acts[w0 + 2][0];
            const float* a3p = &acts[w0 + 3][0];
            #pragma unroll
            for (int d = 0; d < DL; ++d) {
                float2 wv0 = *(const float2*)&wt[d][lane * 2];
                float2 wv1 = *(const float2*)&wt[d][64 + lane * 2];
                float a0 = a0p[d], a1 = a1p[d], a2 = a2p[d], a3 = a3p[d];
                sA[0][0] += a0 * wv0.x; sA[0][1] += a0 * wv0.y;
                sA[1][0] += a1 * wv0.x; sA[1][1] += a1 * wv0.y;
                sA[2][0] += a2 * wv0.x; sA[2][1] += a2 * wv0.y;
                sA[3][0] += a3 * wv0.x; sA[3][1] += a3 * wv0.y;
                sB[0][0] += a0 * wv1.x; sB[0][1] += a0 * wv1.y;
                sB[1][0] += a1 * wv1.x; sB[1][1] += a1 * wv1.y;
                sB[2][0] += a2 * wv1.x; sB[2][1] += a2 * wv1.y;
                sB[3][0] += a3 * wv1.x; sB[3][1] += a3 * wv1.y;
            }
            #pragma unroll
            for (int i = 0; i < 4; ++i) {
                int slot = w0 + i;
                if (slot >= s && slot < r) {
                    int a = sa[slot];
                    float twv = g_tw[a];
                    float* op = &out[(size_t)(a >> 1) * 1024 + m0 + lane * 2];
                    atomicAdd(op,          twv * sA[i][0]);
                    atomicAdd(op + 1,      twv * sA[i][1]);
                    atomicAdd(op + 64,     twv * sB[i][0]);
                    atomicAdd(op + 65,     twv * sB[i][1]);
                }
            }
        }
        s = r;
    }

    // fused aux loss (block 0,0 only; deterministic fixed-order reduction)
    if (has_aux && blockIdx.x == 0 && blockIdx.y == 0) {
        __syncthreads();
        int w = tid >> 5, ln = tid & 31;
        for (int ee = w; ee < NEXP; ee += 8) {
            float psum = 0.f; int ccnt = 0;
            for (int n = ln; n < NTOK; n += 32) {
                psum += g_probs[n * NEXP + ee];
                ccnt += (g_ti[2*n] == ee) + (g_ti[2*n+1] == ee);
            }
            #pragma unroll
            for (int o = 16; o; o >>= 1) {
                psum += __shfl_down_sync(0xffffffffu, psum, o);
                ccnt += __shfl_down_sync(0xffffffffu, ccnt, o);
            }
            if (ln == 0) partial[ee] = psum * (float)ccnt;
        }
        __syncthreads();
        if (tid == 0) {
            float ssum = 0.f;
            #pragma unroll
            for (int q = 0; q < NEXP; ++q) ssum += partial[q];
            out[NTOK * 1024] = ssum * ((float)NEXP / ((float)NTOK * (float)NTOK));
        }
    }
}

// ---------------- launch ---------------------------------------------------
extern "C" void kernel_launch(void* const* d_in, const int* in_sizes, int n_in,
                              void* d_out, int out_size)
{
    const float* x      = (const float*)d_in[0];
    const float* w_down = (const float*)d_in[1];
    const float* pos    = (const float*)d_in[2];
    const float* gp_w   = (const float*)d_in[3];
    const float* gp_b   = (const float*)d_in[4];
    const float* aw     = (const float*)d_in[5];
    const float* ab     = (const float*)d_in[6];
    const float* ow     = (const float*)d_in[7];
    const float* ob     = (const float*)d_in[8];
    const float* lnw    = (const float*)d_in[9];
    const float* lnb    = (const float*)d_in[10];
    const float* lsw    = (const float*)d_in[11];
    const float* lsb    = (const float*)d_in[12];
    const float* g1w    = (const float*)d_in[13];
    const float* g1b    = (const float*)d_in[14];
    const float* g2w    = (const float*)d_in[15];
    const float* g2b    = (const float*)d_in[16];
    const float* wup    = (const float*)d_in[17];
    float* out = (float*)d_out;

    static int attr_done = 0;
    if (!attr_done) {
        cudaFuncSetAttribute(k_ef_mma, cudaFuncAttributeMaxDynamicSharedMemorySize, EF_SMEM);
        attr_done = 1;
    }

    int has_aux = (out_size > NTOK * 1024) ? 1 : 0;

    k_split  <<<2048, 256>>>(x, w_down, out, out_size);
    k_ef_mma <<<516, 128, EF_SMEM>>>(gp_w, gp_b, g1w, g1b, g2w, g2b);
    k_token  <<<NTOK, 256>>>(pos, aw, ab, ow, ob, lnw, lnb, lsw, lsb);
    k_moe2   <<<dim3(NASSIGN / MSLOT, 8), 256>>>(wup, out, has_aux);
}